// round 8
// baseline (speedup 1.0000x reference)
#include <cuda_runtime.h>
#include <cuda_fp16.h>
#include <math.h>

#define NN 50000
#define NE 600000
#define HD 128
#define NG 64
#define HID (NG * 256)
#define SCAN_B 256
#define NBLK ((NN + SCAN_B - 1) / SCAN_B)   // 196

// ---------------- scratch ----------------------------------------------------
__device__ __align__(16) float g_deg[NN];
__device__ __align__(16) float g_self[NN];
__device__ __align__(16) int   g_cnt[NN];
__device__ __align__(16) int   g_ptr[NN + 1];
__device__ __align__(16) int   g_cur[NN];
__device__ __align__(16) int   g_bsum[NBLK];
__device__ __align__(16) int   g_boff[NBLK];
__device__ __align__(16) int   g_srcA[NE];
__device__ __align__(16) float g_normA[NE];
__device__ __align__(16) __half g_t[(size_t)NN * HD];
__device__ __align__(16) float g_hA[(size_t)NN * HD];
__device__ __align__(16) float g_hB[(size_t)NN * HD];
__device__ __align__(16) float g_hidden[HID];
__device__ __align__(16) float g_out[NG];
__device__ int g_gs[NG], g_ge[NG];

// ---------------- setup kernels ---------------------------------------------
__global__ void k_init() {
    int i = blockIdx.x * blockDim.x + threadIdx.x;
    if (i < NN) { g_deg[i] = 2.0f; g_cnt[i] = 0; }
    if (i < NG) { g_gs[i] = 0; g_ge[i] = 0; }
}

__global__ void k_deg(const int* __restrict__ ei, const float* __restrict__ ew) {
    int i = blockIdx.x * blockDim.x + threadIdx.x;
    if (i >= NE) return;
    int d = ei[NE + i];
    if ((unsigned)d >= NN) return;
    atomicAdd(&g_deg[d], ew[i]);
    atomicAdd(&g_cnt[d], 1);
}

// block-sum of counts + dinv/self (fused)
__global__ void k_bsum() {
    __shared__ int sh[SCAN_B];
    int i = blockIdx.x * SCAN_B + threadIdx.x;
    if (i < NN) {
        float dv = rsqrtf(g_deg[i]);
        g_deg[i] = dv;
        g_self[i] = 2.0f * dv * dv;
    }
    sh[threadIdx.x] = (i < NN) ? g_cnt[i] : 0;
    __syncthreads();
    for (int off = SCAN_B / 2; off > 0; off >>= 1) {
        if (threadIdx.x < off) sh[threadIdx.x] += sh[threadIdx.x + off];
        __syncthreads();
    }
    if (threadIdx.x == 0) g_bsum[blockIdx.x] = sh[0];
}

// shuffle-scan of block sums (1 block)
__global__ void k_bscan() {
    __shared__ int wsum[8];
    int t = threadIdx.x;
    int v = (t < NBLK) ? g_bsum[t] : 0;
    int x = v;
#pragma unroll
    for (int o = 1; o < 32; o <<= 1) {
        int y = __shfl_up_sync(0xffffffffu, x, o);
        if ((t & 31) >= o) x += y;
    }
    if ((t & 31) == 31) wsum[t >> 5] = x;
    __syncthreads();
    if (t < 8) {
        int y = wsum[t];
#pragma unroll
        for (int o = 1; o < 8; o <<= 1) {
            int z = __shfl_up_sync(0xffu, y, o);
            if (t >= o) y += z;
        }
        wsum[t] = y;
    }
    __syncthreads();
    int base = (t >= 32) ? wsum[(t >> 5) - 1] : 0;
    int inc = base + x;
    if (t < NBLK) g_boff[t] = inc - v;
    if (t == NBLK - 1) g_ptr[NN] = inc;
}

// row pointers + graph bounds (fused, shuffle scan)
__global__ void k_ptr(const int* __restrict__ batch) {
    __shared__ int wsum[8];
    int i = blockIdx.x * SCAN_B + threadIdx.x;
    int t = threadIdx.x;
    int v = (i < NN) ? g_cnt[i] : 0;
    int x = v;
#pragma unroll
    for (int o = 1; o < 32; o <<= 1) {
        int y = __shfl_up_sync(0xffffffffu, x, o);
        if ((t & 31) >= o) x += y;
    }
    if ((t & 31) == 31) wsum[t >> 5] = x;
    __syncthreads();
    if (t < 8) {
        int y = wsum[t];
#pragma unroll
        for (int o = 1; o < 8; o <<= 1) {
            int z = __shfl_up_sync(0xffu, y, o);
            if (t >= o) y += z;
        }
        wsum[t] = y;
    }
    __syncthreads();
    int base = (t >= 32) ? wsum[(t >> 5) - 1] : 0;
    if (i < NN) {
        int p = g_boff[blockIdx.x] + base + x - v;   // exclusive prefix
        g_ptr[i] = p;
        g_cur[i] = p;
        int g = batch[i];
        if ((unsigned)g < NG) {
            if (i == 0 || batch[i - 1] != g) g_gs[g] = i;
            if (i == NN - 1 || batch[i + 1] != g) g_ge[g] = i + 1;
        }
    }
}

__global__ void k_scatter(const int* __restrict__ ei, const float* __restrict__ ew) {
    int i = blockIdx.x * blockDim.x + threadIdx.x;
    if (i >= NE) return;
    int s = ei[i];
    int d = ei[NE + i];
    if ((unsigned)s >= NN || (unsigned)d >= NN) return;
    int pos = atomicAdd(&g_cur[d], 1);
    if ((unsigned)pos >= NE) return;
    g_srcA[pos] = s;
    g_normA[pos] = g_deg[s] * ew[i] * g_deg[d];
}

// ---------------- TF32 tensor-core GEMM -> fp16 output ----------------------
#define STRA 132
#define STRW 136
#define GEMM_SMEM ((128 * STRW + 128 * STRA) * (int)sizeof(float))

__device__ __forceinline__ unsigned f2tf32(float x) {
    unsigned y;
    asm("cvt.rna.tf32.f32 %0, %1;" : "=r"(y) : "f"(x));
    return y;
}

__device__ __forceinline__ void mma_tf32(float* c, unsigned a0, unsigned a1,
                                         unsigned a2, unsigned a3,
                                         unsigned b0, unsigned b1) {
    asm volatile(
        "mma.sync.aligned.m16n8k8.row.col.f32.tf32.tf32.f32 "
        "{%0,%1,%2,%3}, {%4,%5,%6,%7}, {%8,%9}, {%0,%1,%2,%3};"
        : "+f"(c[0]), "+f"(c[1]), "+f"(c[2]), "+f"(c[3])
        : "r"(a0), "r"(a1), "r"(a2), "r"(a3), "r"(b0), "r"(b1));
}

__global__ __launch_bounds__(256) void k_gemm(const float* __restrict__ A,
                                              const float* __restrict__ W,
                                              __half* __restrict__ O, int nrows) {
    extern __shared__ float sm[];
    float* Ws = sm;
    float* As = sm + 128 * STRW;
    const int tid = threadIdx.x;
    const int row0 = blockIdx.x * 128;

    for (int idx = tid; idx < 128 * 128 / 4; idx += 256) {
        int e = idx * 4;
        int k = e >> 7, n = e & 127;
        float4 v = *(const float4*)(W + e);
        float4 t;
        t.x = __uint_as_float(f2tf32(v.x));
        t.y = __uint_as_float(f2tf32(v.y));
        t.z = __uint_as_float(f2tf32(v.z));
        t.w = __uint_as_float(f2tf32(v.w));
        *(float4*)(Ws + k * STRW + n) = t;
    }
    for (int idx = tid; idx < 128 * 128 / 4; idx += 256) {
        int e = idx * 4;
        int r = e >> 7, k = e & 127;
        int gr = row0 + r;
        float4 v = (gr < nrows) ? *(const float4*)(A + (size_t)gr * HD + k)
                                : make_float4(0.f, 0.f, 0.f, 0.f);
        float4 t;
        t.x = __uint_as_float(f2tf32(v.x));
        t.y = __uint_as_float(f2tf32(v.y));
        t.z = __uint_as_float(f2tf32(v.z));
        t.w = __uint_as_float(f2tf32(v.w));
        *(float4*)(As + r * STRA + k) = t;
    }
    __syncthreads();

    const int wid = tid >> 5, lane = tid & 31;
    const int r = lane >> 2;
    const int c = lane & 3;
    const int warpRow = wid * 16;

    float acc[16][4];
#pragma unroll
    for (int nt = 0; nt < 16; nt++) {
        acc[nt][0] = 0.f; acc[nt][1] = 0.f; acc[nt][2] = 0.f; acc[nt][3] = 0.f;
    }

#pragma unroll
    for (int k0 = 0; k0 < 128; k0 += 8) {
        unsigned a0 = __float_as_uint(As[(warpRow + r) * STRA + k0 + c]);
        unsigned a1 = __float_as_uint(As[(warpRow + r + 8) * STRA + k0 + c]);
        unsigned a2 = __float_as_uint(As[(warpRow + r) * STRA + k0 + c + 4]);
        unsigned a3 = __float_as_uint(As[(warpRow + r + 8) * STRA + k0 + c + 4]);
#pragma unroll
        for (int nt = 0; nt < 16; nt++) {
            int n0 = nt * 8;
            unsigned b0 = __float_as_uint(Ws[(k0 + c) * STRW + n0 + r]);
            unsigned b1 = __float_as_uint(Ws[(k0 + 4 + c) * STRW + n0 + r]);
            mma_tf32(acc[nt], a0, a1, a2, a3, b0, b1);
        }
    }

    int orowA = row0 + warpRow + r;
    int orowB = orowA + 8;
#pragma unroll
    for (int nt = 0; nt < 16; nt++) {
        int n = nt * 8 + c * 2;
        if (orowA < nrows)
            *(__half2*)(O + (size_t)orowA * HD + n) =
                __floats2half2_rn(acc[nt][0], acc[nt][1]);
        if (orowB < nrows)
            *(__half2*)(O + (size_t)orowB * HD + n) =
                __floats2half2_rn(acc[nt][2], acc[nt][3]);
    }
}

// ---------------- aggregation: warp/node, 8-edge unroll (MLP=8) -------------
__global__ void k_aggr(const __half* __restrict__ T, const float* __restrict__ bias,
                       float* __restrict__ Hout) {
    int gw = (blockIdx.x * blockDim.x + threadIdx.x) >> 5;
    if (gw >= NN) return;
    const int lane = threadIdx.x & 31;
    const int c = lane << 2;

    float sn = g_self[gw];
    uint2 tr = *(const uint2*)(T + (size_t)gw * HD + c);
    float2 ta = __half22float2(*(__half2*)&tr.x);
    float2 tb = __half22float2(*(__half2*)&tr.y);
    float4 acc = make_float4(ta.x * sn, ta.y * sn, tb.x * sn, tb.y * sn);

    int e = g_ptr[gw];
    const int e1 = g_ptr[gw + 1];

    for (; e + 8 <= e1; e += 8) {
        int s[8];
        float w[8];
        uint2 rr[8];
#pragma unroll
        for (int j = 0; j < 8; j++) { s[j] = g_srcA[e + j]; w[j] = g_normA[e + j]; }
#pragma unroll
        for (int j = 0; j < 8; j++)
            rr[j] = *(const uint2*)(T + (size_t)s[j] * HD + c);
#pragma unroll
        for (int j = 0; j < 8; j++) {
            float2 aa = __half22float2(*(__half2*)&rr[j].x);
            float2 bb = __half22float2(*(__half2*)&rr[j].y);
            acc.x += w[j] * aa.x;
            acc.y += w[j] * aa.y;
            acc.z += w[j] * bb.x;
            acc.w += w[j] * bb.y;
        }
    }
    for (; e < e1; e++) {
        int s = g_srcA[e];
        float w = g_normA[e];
        uint2 rr = *(const uint2*)(T + (size_t)s * HD + c);
        float2 aa = __half22float2(*(__half2*)&rr.x);
        float2 bb = __half22float2(*(__half2*)&rr.y);
        acc.x += w * aa.x; acc.y += w * aa.y; acc.z += w * bb.x; acc.w += w * bb.y;
    }
    float4 bb = *(const float4*)(bias + c);
    float4 o;
    o.x = tanhf(acc.x + bb.x);
    o.y = tanhf(acc.y + bb.y);
    o.z = tanhf(acc.z + bb.z);
    o.w = tanhf(acc.w + bb.w);
    *(float4*)(Hout + (size_t)gw * HD + c) = o;
}

// ---------------- readout ----------------------------------------------------
__global__ void k_readout(const float* __restrict__ Hl) {
    int g = blockIdx.x;
    int c = threadIdx.x;
    int s = g_gs[g], e = g_ge[g];
    float vmax = -INFINITY, vsum = 0.0f;
    for (int i = s; i < e; i++) {
        float v = Hl[(size_t)i * HD + c];
        vmax = fmaxf(vmax, v);
        vsum += v;
    }
    int cnt = e - s;
    g_hidden[(size_t)g * 256 + c] = (cnt > 0) ? vmax : 0.0f;
    g_hidden[(size_t)g * 256 + 128 + c] = vsum / fmaxf((float)cnt, 1.0f);
}

__global__ void k_final(const float* __restrict__ Wout, const float* __restrict__ bout) {
    __shared__ float red[256];
    int g = blockIdx.x, t = threadIdx.x;
    red[t] = g_hidden[(size_t)g * 256 + t] * Wout[t];
    __syncthreads();
    for (int off = 128; off > 0; off >>= 1) {
        if (t < off) red[t] += red[t + off];
        __syncthreads();
    }
    if (t == 0) g_out[g] = red[0] + bout[0];
}

// ---------------- emit -------------------------------------------------------
__global__ void k_emit(float* __restrict__ out, int out_size) {
    int i = blockIdx.x * blockDim.x + threadIdx.x;
    if (i >= out_size) return;
    float v;
    if (out_size >= NG + HID) {
        v = (i < NG) ? g_out[i] : g_hidden[i - NG];
    } else if (out_size == HID) {
        v = g_hidden[i];
    } else {
        v = (i < NG) ? g_out[i] : 0.0f;
    }
    out[i] = v;
}

// ---------------- launch -----------------------------------------------------
extern "C" void kernel_launch(void* const* d_in, const int* in_sizes, int n_in,
                              void* d_out, int out_size) {
    const float* x     = (const float*)d_in[0];
    const int*   ei    = (const int*)d_in[1];
    const int*   batch = (const int*)d_in[2];
    const float* ew    = (const float*)d_in[3];
    const float* W[4] = { (const float*)d_in[4], (const float*)d_in[6],
                          (const float*)d_in[8], (const float*)d_in[10] };
    const float* B[4] = { (const float*)d_in[5], (const float*)d_in[7],
                          (const float*)d_in[9], (const float*)d_in[11] };
    const float* Wout = (const float*)d_in[12];
    const float* bout = (const float*)d_in[13];

    cudaFuncSetAttribute(k_gemm, cudaFuncAttributeMaxDynamicSharedMemorySize, GEMM_SMEM);

    __half* tbuf;
    float *hA, *hB;
    cudaGetSymbolAddress((void**)&tbuf, g_t);
    cudaGetSymbolAddress((void**)&hA, g_hA);
    cudaGetSymbolAddress((void**)&hB, g_hB);

    k_init<<<(NN + 255) / 256, 256>>>();
    k_deg<<<(NE + 255) / 256, 256>>>(ei, ew);
    k_bsum<<<NBLK, SCAN_B>>>();
    k_bscan<<<1, SCAN_B>>>();
    k_ptr<<<NBLK, SCAN_B>>>(batch);
    k_scatter<<<(NE + 255) / 256, 256>>>(ei, ew);

    const int gemm_grid = (NN + 127) / 128;
    const int aggr_grid = (NN * 32 + 255) / 256;

    const float* cur = x;
    float* ping[4] = { hA, hB, hA, hB };
    for (int l = 0; l < 4; l++) {
        k_gemm<<<gemm_grid, 256, GEMM_SMEM>>>(cur, W[l], tbuf, NN);
        k_aggr<<<aggr_grid, 256>>>(tbuf, B[l], ping[l]);
        cur = ping[l];
    }

    k_readout<<<NG, 128>>>(cur);
    k_final<<<NG, 256>>>(Wout, bout);
    k_emit<<<(out_size + 255) / 256, 256>>>((float*)d_out, out_size);
}

// round 9
// speedup vs baseline: 1.3107x; 1.3107x over previous
#include <cuda_runtime.h>
#include <cuda_fp16.h>
#include <math.h>

#define NN 50000
#define NE 600000
#define HD 128
#define NG 64
#define HID (NG * 256)
#define SCAN_B 256
#define NBLK ((NN + SCAN_B - 1) / SCAN_B)   // 196

// ---------------- scratch ----------------------------------------------------
__device__ __align__(16) float g_deg[NN];
__device__ __align__(16) float g_self[NN];
__device__ __align__(16) int   g_cnt[NN];
__device__ __align__(16) int   g_ptr[NN + 1];
__device__ __align__(16) int   g_cur[NN];
__device__ __align__(16) int   g_bsum[NBLK];
__device__ __align__(16) int   g_boff[NBLK];
__device__ __align__(16) int   g_srcA[NE];
__device__ __align__(16) float g_normA[NE];
__device__ __align__(16) __half g_t[(size_t)NN * HD];
__device__ __align__(16) float g_hA[(size_t)NN * HD];
__device__ __align__(16) float g_hB[(size_t)NN * HD];
__device__ __align__(16) float g_hidden[HID];
__device__ __align__(16) float g_out[NG];
__device__ int g_gs[NG], g_ge[NG];

// ---------------- setup kernels ---------------------------------------------
__global__ void k_init() {
    int i = blockIdx.x * blockDim.x + threadIdx.x;
    if (i < NN) { g_deg[i] = 2.0f; g_cnt[i] = 0; }
    if (i < NG) { g_gs[i] = 0; g_ge[i] = 0; }
}

__global__ void k_deg(const int* __restrict__ ei, const float* __restrict__ ew) {
    int i = blockIdx.x * blockDim.x + threadIdx.x;
    if (i >= NE) return;
    int d = ei[NE + i];
    if ((unsigned)d >= NN) return;
    atomicAdd(&g_deg[d], ew[i]);
    atomicAdd(&g_cnt[d], 1);
}

__global__ void k_bsum() {
    __shared__ int sh[SCAN_B];
    int i = blockIdx.x * SCAN_B + threadIdx.x;
    if (i < NN) {
        float dv = rsqrtf(g_deg[i]);
        g_deg[i] = dv;
        g_self[i] = 2.0f * dv * dv;
    }
    sh[threadIdx.x] = (i < NN) ? g_cnt[i] : 0;
    __syncthreads();
    for (int off = SCAN_B / 2; off > 0; off >>= 1) {
        if (threadIdx.x < off) sh[threadIdx.x] += sh[threadIdx.x + off];
        __syncthreads();
    }
    if (threadIdx.x == 0) g_bsum[blockIdx.x] = sh[0];
}

__global__ void k_bscan() {
    __shared__ int wsum[8];
    int t = threadIdx.x;
    int v = (t < NBLK) ? g_bsum[t] : 0;
    int x = v;
#pragma unroll
    for (int o = 1; o < 32; o <<= 1) {
        int y = __shfl_up_sync(0xffffffffu, x, o);
        if ((t & 31) >= o) x += y;
    }
    if ((t & 31) == 31) wsum[t >> 5] = x;
    __syncthreads();
    if (t < 8) {
        int y = wsum[t];
#pragma unroll
        for (int o = 1; o < 8; o <<= 1) {
            int z = __shfl_up_sync(0xffu, y, o);
            if (t >= o) y += z;
        }
        wsum[t] = y;
    }
    __syncthreads();
    int base = (t >= 32) ? wsum[(t >> 5) - 1] : 0;
    int inc = base + x;
    if (t < NBLK) g_boff[t] = inc - v;
    if (t == NBLK - 1) g_ptr[NN] = inc;
}

__global__ void k_ptr(const int* __restrict__ batch) {
    __shared__ int wsum[8];
    int i = blockIdx.x * SCAN_B + threadIdx.x;
    int t = threadIdx.x;
    int v = (i < NN) ? g_cnt[i] : 0;
    int x = v;
#pragma unroll
    for (int o = 1; o < 32; o <<= 1) {
        int y = __shfl_up_sync(0xffffffffu, x, o);
        if ((t & 31) >= o) x += y;
    }
    if ((t & 31) == 31) wsum[t >> 5] = x;
    __syncthreads();
    if (t < 8) {
        int y = wsum[t];
#pragma unroll
        for (int o = 1; o < 8; o <<= 1) {
            int z = __shfl_up_sync(0xffu, y, o);
            if (t >= o) y += z;
        }
        wsum[t] = y;
    }
    __syncthreads();
    int base = (t >= 32) ? wsum[(t >> 5) - 1] : 0;
    if (i < NN) {
        int p = g_boff[blockIdx.x] + base + x - v;
        g_ptr[i] = p;
        g_cur[i] = p;
        int g = batch[i];
        if ((unsigned)g < NG) {
            if (i == 0 || batch[i - 1] != g) g_gs[g] = i;
            if (i == NN - 1 || batch[i + 1] != g) g_ge[g] = i + 1;
        }
    }
}

__global__ void k_scatter(const int* __restrict__ ei, const float* __restrict__ ew) {
    int i = blockIdx.x * blockDim.x + threadIdx.x;
    if (i >= NE) return;
    int s = ei[i];
    int d = ei[NE + i];
    if ((unsigned)s >= NN || (unsigned)d >= NN) return;
    int pos = atomicAdd(&g_cur[d], 1);
    if ((unsigned)pos >= NE) return;
    g_srcA[pos] = s;
    g_normA[pos] = g_deg[s] * ew[i] * g_deg[d];
}

// ---------------- TF32 tensor-core GEMM -> fp16 output ----------------------
#define STRA 132
#define STRW 136
#define GEMM_SMEM ((128 * STRW + 128 * STRA) * (int)sizeof(float))

__device__ __forceinline__ unsigned f2tf32(float x) {
    unsigned y;
    asm("cvt.rna.tf32.f32 %0, %1;" : "=r"(y) : "f"(x));
    return y;
}

__device__ __forceinline__ void mma_tf32(float* c, unsigned a0, unsigned a1,
                                         unsigned a2, unsigned a3,
                                         unsigned b0, unsigned b1) {
    asm volatile(
        "mma.sync.aligned.m16n8k8.row.col.f32.tf32.tf32.f32 "
        "{%0,%1,%2,%3}, {%4,%5,%6,%7}, {%8,%9}, {%0,%1,%2,%3};"
        : "+f"(c[0]), "+f"(c[1]), "+f"(c[2]), "+f"(c[3])
        : "r"(a0), "r"(a1), "r"(a2), "r"(a3), "r"(b0), "r"(b1));
}

__global__ __launch_bounds__(256) void k_gemm(const float* __restrict__ A,
                                              const float* __restrict__ W,
                                              __half* __restrict__ O, int nrows) {
    extern __shared__ float sm[];
    float* Ws = sm;
    float* As = sm + 128 * STRW;
    const int tid = threadIdx.x;
    const int row0 = blockIdx.x * 128;

    for (int idx = tid; idx < 128 * 128 / 4; idx += 256) {
        int e = idx * 4;
        int k = e >> 7, n = e & 127;
        float4 v = *(const float4*)(W + e);
        float4 t;
        t.x = __uint_as_float(f2tf32(v.x));
        t.y = __uint_as_float(f2tf32(v.y));
        t.z = __uint_as_float(f2tf32(v.z));
        t.w = __uint_as_float(f2tf32(v.w));
        *(float4*)(Ws + k * STRW + n) = t;
    }
    for (int idx = tid; idx < 128 * 128 / 4; idx += 256) {
        int e = idx * 4;
        int r = e >> 7, k = e & 127;
        int gr = row0 + r;
        float4 v = (gr < nrows) ? *(const float4*)(A + (size_t)gr * HD + k)
                                : make_float4(0.f, 0.f, 0.f, 0.f);
        float4 t;
        t.x = __uint_as_float(f2tf32(v.x));
        t.y = __uint_as_float(f2tf32(v.y));
        t.z = __uint_as_float(f2tf32(v.z));
        t.w = __uint_as_float(f2tf32(v.w));
        *(float4*)(As + r * STRA + k) = t;
    }
    __syncthreads();

    const int wid = tid >> 5, lane = tid & 31;
    const int r = lane >> 2;
    const int c = lane & 3;
    const int warpRow = wid * 16;

    float acc[16][4];
#pragma unroll
    for (int nt = 0; nt < 16; nt++) {
        acc[nt][0] = 0.f; acc[nt][1] = 0.f; acc[nt][2] = 0.f; acc[nt][3] = 0.f;
    }

#pragma unroll
    for (int k0 = 0; k0 < 128; k0 += 8) {
        unsigned a0 = __float_as_uint(As[(warpRow + r) * STRA + k0 + c]);
        unsigned a1 = __float_as_uint(As[(warpRow + r + 8) * STRA + k0 + c]);
        unsigned a2 = __float_as_uint(As[(warpRow + r) * STRA + k0 + c + 4]);
        unsigned a3 = __float_as_uint(As[(warpRow + r + 8) * STRA + k0 + c + 4]);
#pragma unroll
        for (int nt = 0; nt < 16; nt++) {
            int n0 = nt * 8;
            unsigned b0 = __float_as_uint(Ws[(k0 + c) * STRW + n0 + r]);
            unsigned b1 = __float_as_uint(Ws[(k0 + 4 + c) * STRW + n0 + r]);
            mma_tf32(acc[nt], a0, a1, a2, a3, b0, b1);
        }
    }

    int orowA = row0 + warpRow + r;
    int orowB = orowA + 8;
#pragma unroll
    for (int nt = 0; nt < 16; nt++) {
        int n = nt * 8 + c * 2;
        if (orowA < nrows)
            *(__half2*)(O + (size_t)orowA * HD + n) =
                __floats2half2_rn(acc[nt][0], acc[nt][1]);
        if (orowB < nrows)
            *(__half2*)(O + (size_t)orowB * HD + n) =
                __floats2half2_rn(acc[nt][2], acc[nt][3]);
    }
}

// ---------------- aggregation: warp/node, half-warp rows, 8 edges in flight -
// Each 16-lane half covers the full 128-col row via uint4 (8 halves/lane).
// Half h processes edges e+2j+h -> 4 loads put 8 edge rows in flight.
__global__ void k_aggr(const __half* __restrict__ T, const float* __restrict__ bias,
                       float* __restrict__ Hout) {
    int gw = (blockIdx.x * blockDim.x + threadIdx.x) >> 5;
    if (gw >= NN) return;
    const int lane = threadIdx.x & 31;
    const int half = lane >> 4;        // 0 or 1
    const int sub = lane & 15;
    const int co = sub << 3;           // column offset in halves (8 per lane)

    float acc[8];
    if (half == 0) {
        float sn = g_self[gw];
        uint4 tq = *(const uint4*)(T + (size_t)gw * HD + co);
        const __half2* tp = (const __half2*)&tq;
#pragma unroll
        for (int k = 0; k < 4; k++) {
            float2 f = __half22float2(tp[k]);
            acc[2 * k] = sn * f.x;
            acc[2 * k + 1] = sn * f.y;
        }
    } else {
#pragma unroll
        for (int k = 0; k < 8; k++) acc[k] = 0.f;
    }

    int e = g_ptr[gw];
    const int e1 = g_ptr[gw + 1];

    for (; e + 8 <= e1; e += 8) {
        int s[4];
        float w[4];
#pragma unroll
        for (int j = 0; j < 4; j++) {
            int ed = e + 2 * j + half;
            s[j] = g_srcA[ed];
            w[j] = g_normA[ed];
        }
        uint4 rr[4];
#pragma unroll
        for (int j = 0; j < 4; j++)
            rr[j] = *(const uint4*)(T + (size_t)s[j] * HD + co);
#pragma unroll
        for (int j = 0; j < 4; j++) {
            const __half2* rp = (const __half2*)&rr[j];
#pragma unroll
            for (int k = 0; k < 4; k++) {
                float2 f = __half22float2(rp[k]);
                acc[2 * k] += w[j] * f.x;
                acc[2 * k + 1] += w[j] * f.y;
            }
        }
    }
    // tail: half 0 only, one edge at a time
    if (half == 0) {
        for (int et = e; et < e1; et++) {
            int s = g_srcA[et];
            float w = g_normA[et];
            uint4 rr = *(const uint4*)(T + (size_t)s * HD + co);
            const __half2* rp = (const __half2*)&rr;
#pragma unroll
            for (int k = 0; k < 4; k++) {
                float2 f = __half22float2(rp[k]);
                acc[2 * k] += w * f.x;
                acc[2 * k + 1] += w * f.y;
            }
        }
    }
    // combine halves
#pragma unroll
    for (int k = 0; k < 8; k++)
        acc[k] += __shfl_xor_sync(0xffffffffu, acc[k], 16);

    if (half == 0) {
        float4 b0 = *(const float4*)(bias + co);
        float4 b1 = *(const float4*)(bias + co + 4);
        float4 o0, o1;
        o0.x = tanhf(acc[0] + b0.x);
        o0.y = tanhf(acc[1] + b0.y);
        o0.z = tanhf(acc[2] + b0.z);
        o0.w = tanhf(acc[3] + b0.w);
        o1.x = tanhf(acc[4] + b1.x);
        o1.y = tanhf(acc[5] + b1.y);
        o1.z = tanhf(acc[6] + b1.z);
        o1.w = tanhf(acc[7] + b1.w);
        *(float4*)(Hout + (size_t)gw * HD + co) = o0;
        *(float4*)(Hout + (size_t)gw * HD + co + 4) = o1;
    }
}

// ---------------- readout ----------------------------------------------------
__global__ void k_readout(const float* __restrict__ Hl) {
    int g = blockIdx.x;
    int c = threadIdx.x;
    int s = g_gs[g], e = g_ge[g];
    float vmax = -INFINITY, vsum = 0.0f;
    for (int i = s; i < e; i++) {
        float v = Hl[(size_t)i * HD + c];
        vmax = fmaxf(vmax, v);
        vsum += v;
    }
    int cnt = e - s;
    g_hidden[(size_t)g * 256 + c] = (cnt > 0) ? vmax : 0.0f;
    g_hidden[(size_t)g * 256 + 128 + c] = vsum / fmaxf((float)cnt, 1.0f);
}

__global__ void k_final(const float* __restrict__ Wout, const float* __restrict__ bout) {
    __shared__ float red[256];
    int g = blockIdx.x, t = threadIdx.x;
    red[t] = g_hidden[(size_t)g * 256 + t] * Wout[t];
    __syncthreads();
    for (int off = 128; off > 0; off >>= 1) {
        if (t < off) red[t] += red[t + off];
        __syncthreads();
    }
    if (t == 0) g_out[g] = red[0] + bout[0];
}

// ---------------- emit -------------------------------------------------------
__global__ void k_emit(float* __restrict__ out, int out_size) {
    int i = blockIdx.x * blockDim.x + threadIdx.x;
    if (i >= out_size) return;
    float v;
    if (out_size >= NG + HID) {
        v = (i < NG) ? g_out[i] : g_hidden[i - NG];
    } else if (out_size == HID) {
        v = g_hidden[i];
    } else {
        v = (i < NG) ? g_out[i] : 0.0f;
    }
    out[i] = v;
}

// ---------------- launch -----------------------------------------------------
extern "C" void kernel_launch(void* const* d_in, const int* in_sizes, int n_in,
                              void* d_out, int out_size) {
    const float* x     = (const float*)d_in[0];
    const int*   ei    = (const int*)d_in[1];
    const int*   batch = (const int*)d_in[2];
    const float* ew    = (const float*)d_in[3];
    const float* W[4] = { (const float*)d_in[4], (const float*)d_in[6],
                          (const float*)d_in[8], (const float*)d_in[10] };
    const float* B[4] = { (const float*)d_in[5], (const float*)d_in[7],
                          (const float*)d_in[9], (const float*)d_in[11] };
    const float* Wout = (const float*)d_in[12];
    const float* bout = (const float*)d_in[13];

    cudaFuncSetAttribute(k_gemm, cudaFuncAttributeMaxDynamicSharedMemorySize, GEMM_SMEM);

    __half* tbuf;
    float *hA, *hB;
    cudaGetSymbolAddress((void**)&tbuf, g_t);
    cudaGetSymbolAddress((void**)&hA, g_hA);
    cudaGetSymbolAddress((void**)&hB, g_hB);

    k_init<<<(NN + 255) / 256, 256>>>();
    k_deg<<<(NE + 255) / 256, 256>>>(ei, ew);
    k_bsum<<<NBLK, SCAN_B>>>();
    k_bscan<<<1, SCAN_B>>>();
    k_ptr<<<NBLK, SCAN_B>>>(batch);
    k_scatter<<<(NE + 255) / 256, 256>>>(ei, ew);

    const int gemm_grid = (NN + 127) / 128;
    const int aggr_grid = (NN * 32 + 255) / 256;

    const float* cur = x;
    float* ping[4] = { hA, hB, hA, hB };
    for (int l = 0; l < 4; l++) {
        k_gemm<<<gemm_grid, 256, GEMM_SMEM>>>(cur, W[l], tbuf, NN);
        k_aggr<<<aggr_grid, 256>>>(tbuf, B[l], ping[l]);
        cur = ping[l];
    }

    k_readout<<<NG, 128>>>(cur);
    k_final<<<NG, 256>>>(Wout, bout);
    k_emit<<<(out_size + 255) / 256, 256>>>((float*)d_out, out_size);
}

// round 10
// speedup vs baseline: 2.2220x; 1.6953x over previous
#include <cuda_runtime.h>
#include <cuda_fp16.h>
#include <math.h>

#define NN 50000
#define NE 600000
#define HD 128
#define NG 64
#define HID (NG * 256)
#define SCAN_B 256
#define NBLK ((NN + SCAN_B - 1) / SCAN_B)   // 196

// ---------------- scratch ----------------------------------------------------
__device__ __align__(16) float g_deg[NN];
__device__ __align__(16) float g_self[NN];
__device__ __align__(16) int   g_cnt[NN];
__device__ __align__(16) int   g_ptr[NN + 1];
__device__ __align__(16) int   g_cur[NN];
__device__ __align__(16) int   g_bsum[NBLK];
__device__ __align__(16) int   g_boff[NBLK];
__device__ __align__(16) int   g_srcA[NE];
__device__ __align__(16) float g_normA[NE];
__device__ __align__(16) __half g_wt[4 * 128 * 128];   // W^T per layer, half [n][k]
__device__ __align__(16) __half g_t[(size_t)NN * HD];
__device__ __align__(16) float g_hA[(size_t)NN * HD];
__device__ __align__(16) float g_hB[(size_t)NN * HD];
__device__ __align__(16) float g_hidden[HID];
__device__ __align__(16) float g_out[NG];
__device__ int g_gs[NG], g_ge[NG];

// ---------------- setup kernels ---------------------------------------------
__global__ void k_init() {
    int i = blockIdx.x * blockDim.x + threadIdx.x;
    if (i < NN) { g_deg[i] = 2.0f; g_cnt[i] = 0; }
    if (i < NG) { g_gs[i] = 0; g_ge[i] = 0; }
}

__global__ void k_deg(const int* __restrict__ ei, const float* __restrict__ ew) {
    int i = blockIdx.x * blockDim.x + threadIdx.x;
    if (i >= NE) return;
    int d = ei[NE + i];
    if ((unsigned)d >= NN) return;
    atomicAdd(&g_deg[d], ew[i]);
    atomicAdd(&g_cnt[d], 1);
}

__global__ void k_bsum() {
    __shared__ int sh[SCAN_B];
    int i = blockIdx.x * SCAN_B + threadIdx.x;
    if (i < NN) {
        float dv = rsqrtf(g_deg[i]);
        g_deg[i] = dv;
        g_self[i] = 2.0f * dv * dv;
    }
    sh[threadIdx.x] = (i < NN) ? g_cnt[i] : 0;
    __syncthreads();
    for (int off = SCAN_B / 2; off > 0; off >>= 1) {
        if (threadIdx.x < off) sh[threadIdx.x] += sh[threadIdx.x + off];
        __syncthreads();
    }
    if (threadIdx.x == 0) g_bsum[blockIdx.x] = sh[0];
}

__global__ void k_bscan() {
    __shared__ int wsum[8];
    int t = threadIdx.x;
    int v = (t < NBLK) ? g_bsum[t] : 0;
    int x = v;
#pragma unroll
    for (int o = 1; o < 32; o <<= 1) {
        int y = __shfl_up_sync(0xffffffffu, x, o);
        if ((t & 31) >= o) x += y;
    }
    if ((t & 31) == 31) wsum[t >> 5] = x;
    __syncthreads();
    if (t < 8) {
        int y = wsum[t];
#pragma unroll
        for (int o = 1; o < 8; o <<= 1) {
            int z = __shfl_up_sync(0xffu, y, o);
            if (t >= o) y += z;
        }
        wsum[t] = y;
    }
    __syncthreads();
    int base = (t >= 32) ? wsum[(t >> 5) - 1] : 0;
    int inc = base + x;
    if (t < NBLK) g_boff[t] = inc - v;
    if (t == NBLK - 1) g_ptr[NN] = inc;
}

__global__ void k_ptr(const int* __restrict__ batch) {
    __shared__ int wsum[8];
    int i = blockIdx.x * SCAN_B + threadIdx.x;
    int t = threadIdx.x;
    int v = (i < NN) ? g_cnt[i] : 0;
    int x = v;
#pragma unroll
    for (int o = 1; o < 32; o <<= 1) {
        int y = __shfl_up_sync(0xffffffffu, x, o);
        if ((t & 31) >= o) x += y;
    }
    if ((t & 31) == 31) wsum[t >> 5] = x;
    __syncthreads();
    if (t < 8) {
        int y = wsum[t];
#pragma unroll
        for (int o = 1; o < 8; o <<= 1) {
            int z = __shfl_up_sync(0xffu, y, o);
            if (t >= o) y += z;
        }
        wsum[t] = y;
    }
    __syncthreads();
    int base = (t >= 32) ? wsum[(t >> 5) - 1] : 0;
    if (i < NN) {
        int p = g_boff[blockIdx.x] + base + x - v;
        g_ptr[i] = p;
        g_cur[i] = p;
        int g = batch[i];
        if ((unsigned)g < NG) {
            if (i == 0 || batch[i - 1] != g) g_gs[g] = i;
            if (i == NN - 1 || batch[i + 1] != g) g_ge[g] = i + 1;
        }
    }
}

__global__ void k_scatter(const int* __restrict__ ei, const float* __restrict__ ew) {
    int i = blockIdx.x * blockDim.x + threadIdx.x;
    if (i >= NE) return;
    int s = ei[i];
    int d = ei[NE + i];
    if ((unsigned)s >= NN || (unsigned)d >= NN) return;
    int pos = atomicAdd(&g_cur[d], 1);
    if ((unsigned)pos >= NE) return;
    g_srcA[pos] = s;
    g_normA[pos] = g_deg[s] * ew[i] * g_deg[d];
}

// transpose + convert all 4 weight matrices to half [n][k]
__global__ void k_wt(const float* __restrict__ W0, const float* __restrict__ W1,
                     const float* __restrict__ W2, const float* __restrict__ W3) {
    int idx = blockIdx.x * blockDim.x + threadIdx.x;   // 0..16383
    if (idx >= 128 * 128) return;
    int k = idx >> 7, n = idx & 127;
    g_wt[0 * 16384 + n * 128 + k] = __float2half(W0[idx]);
    g_wt[1 * 16384 + n * 128 + k] = __float2half(W1[idx]);
    g_wt[2 * 16384 + n * 128 + k] = __float2half(W2[idx]);
    g_wt[3 * 16384 + n * 128 + k] = __float2half(W3[idx]);
}

// ---------------- FP16 tensor-core GEMM: O[n,128] = A @ W, fp32 accum -------
// smem: Wn half [n=128][SK=136], As half [r=128][SK=136]; 68KB -> 3 blocks/SM.
#define SK 136
#define GEMM_SMEM (2 * 128 * SK * (int)sizeof(__half))

__device__ __forceinline__ void mma_f16(float* c, unsigned a0, unsigned a1,
                                        unsigned a2, unsigned a3,
                                        unsigned b0, unsigned b1) {
    asm volatile(
        "mma.sync.aligned.m16n8k16.row.col.f32.f16.f16.f32 "
        "{%0,%1,%2,%3}, {%4,%5,%6,%7}, {%8,%9}, {%0,%1,%2,%3};"
        : "+f"(c[0]), "+f"(c[1]), "+f"(c[2]), "+f"(c[3])
        : "r"(a0), "r"(a1), "r"(a2), "r"(a3), "r"(b0), "r"(b1));
}

__global__ __launch_bounds__(256) void k_gemm(const float* __restrict__ A,
                                              const __half* __restrict__ Wt,
                                              __half* __restrict__ O, int nrows) {
    extern __shared__ __half smh[];
    __half* Wn = smh;            // [n][SK]
    __half* As = smh + 128 * SK; // [r][SK]
    const int tid = threadIdx.x;
    const int row0 = blockIdx.x * 128;

    // Wn fill: pure vector copy, Wt row n (256B) -> smem row n (stride 272B)
#pragma unroll
    for (int i = 0; i < 8; i++) {
        int u = tid + i * 256;         // 0..2047
        int n = u >> 4, kq = u & 15;
        *(uint4*)(Wn + n * SK + kq * 8) = *(const uint4*)(Wt + n * 128 + kq * 8);
    }
    // As fill: fp32 -> half conversion, vectorized
#pragma unroll
    for (int i = 0; i < 8; i++) {
        int u = tid + i * 256;
        int r = u >> 4, kq = u & 15;
        int gr = row0 + r;
        float4 v0, v1;
        if (gr < nrows) {
            v0 = *(const float4*)(A + (size_t)gr * HD + kq * 8);
            v1 = *(const float4*)(A + (size_t)gr * HD + kq * 8 + 4);
        } else {
            v0 = make_float4(0.f, 0.f, 0.f, 0.f);
            v1 = v0;
        }
        __half2 h[4];
        h[0] = __floats2half2_rn(v0.x, v0.y);
        h[1] = __floats2half2_rn(v0.z, v0.w);
        h[2] = __floats2half2_rn(v1.x, v1.y);
        h[3] = __floats2half2_rn(v1.z, v1.w);
        *(uint4*)(As + r * SK + kq * 8) = *(uint4*)h;
    }
    __syncthreads();

    const int wid = tid >> 5, lane = tid & 31;
    const int r = lane >> 2;     // 0..7
    const int q = lane & 3;      // 0..3
    const int warpRow = wid * 16;

    float acc[16][4];
#pragma unroll
    for (int nt = 0; nt < 16; nt++) {
        acc[nt][0] = 0.f; acc[nt][1] = 0.f; acc[nt][2] = 0.f; acc[nt][3] = 0.f;
    }

#pragma unroll
    for (int k0 = 0; k0 < 128; k0 += 16) {
        unsigned a0 = *(const unsigned*)(As + (warpRow + r) * SK + k0 + q * 2);
        unsigned a1 = *(const unsigned*)(As + (warpRow + r + 8) * SK + k0 + q * 2);
        unsigned a2 = *(const unsigned*)(As + (warpRow + r) * SK + k0 + q * 2 + 8);
        unsigned a3 = *(const unsigned*)(As + (warpRow + r + 8) * SK + k0 + q * 2 + 8);
#pragma unroll
        for (int nt = 0; nt < 16; nt++) {
            int n0 = nt * 8;
            unsigned b0 = *(const unsigned*)(Wn + (n0 + r) * SK + k0 + q * 2);
            unsigned b1 = *(const unsigned*)(Wn + (n0 + r) * SK + k0 + q * 2 + 8);
            mma_f16(acc[nt], a0, a1, a2, a3, b0, b1);
        }
    }

    int orowA = row0 + warpRow + r;
    int orowB = orowA + 8;
#pragma unroll
    for (int nt = 0; nt < 16; nt++) {
        int n = nt * 8 + q * 2;
        if (orowA < nrows)
            *(__half2*)(O + (size_t)orowA * HD + n) =
                __floats2half2_rn(acc[nt][0], acc[nt][1]);
        if (orowB < nrows)
            *(__half2*)(O + (size_t)orowB * HD + n) =
                __floats2half2_rn(acc[nt][2], acc[nt][3]);
    }
}

// ---------------- aggregation: one warp per destination (Round-6 form) ------
__global__ void k_aggr(const __half* __restrict__ T, const float* __restrict__ bias,
                       float* __restrict__ Hout) {
    int gw = (blockIdx.x * blockDim.x + threadIdx.x) >> 5;
    if (gw >= NN) return;
    const int lane = threadIdx.x & 31;
    const int c = lane << 2;

    float sn = g_self[gw];
    uint2 tr = *(const uint2*)(T + (size_t)gw * HD + c);
    float2 ta = __half22float2(*(__half2*)&tr.x);
    float2 tb = __half22float2(*(__half2*)&tr.y);
    float4 acc = make_float4(ta.x * sn, ta.y * sn, tb.x * sn, tb.y * sn);

    int e = g_ptr[gw];
    const int e1 = g_ptr[gw + 1];
    for (; e + 3 < e1; e += 4) {
        int s0 = g_srcA[e], s1 = g_srcA[e + 1], s2 = g_srcA[e + 2], s3 = g_srcA[e + 3];
        float w0 = g_normA[e], w1 = g_normA[e + 1], w2 = g_normA[e + 2], w3 = g_normA[e + 3];
        uint2 r0 = *(const uint2*)(T + (size_t)s0 * HD + c);
        uint2 r1 = *(const uint2*)(T + (size_t)s1 * HD + c);
        uint2 r2 = *(const uint2*)(T + (size_t)s2 * HD + c);
        uint2 r3 = *(const uint2*)(T + (size_t)s3 * HD + c);
        float2 a0 = __half22float2(*(__half2*)&r0.x), b0 = __half22float2(*(__half2*)&r0.y);
        float2 a1 = __half22float2(*(__half2*)&r1.x), b1 = __half22float2(*(__half2*)&r1.y);
        float2 a2 = __half22float2(*(__half2*)&r2.x), b2 = __half22float2(*(__half2*)&r2.y);
        float2 a3 = __half22float2(*(__half2*)&r3.x), b3 = __half22float2(*(__half2*)&r3.y);
        acc.x += w0 * a0.x + w1 * a1.x + w2 * a2.x + w3 * a3.x;
        acc.y += w0 * a0.y + w1 * a1.y + w2 * a2.y + w3 * a3.y;
        acc.z += w0 * b0.x + w1 * b1.x + w2 * b2.x + w3 * b3.x;
        acc.w += w0 * b0.y + w1 * b1.y + w2 * b2.y + w3 * b3.y;
    }
    for (; e < e1; e++) {
        int s = g_srcA[e];
        float w = g_normA[e];
        uint2 rr = *(const uint2*)(T + (size_t)s * HD + c);
        float2 aa = __half22float2(*(__half2*)&rr.x);
        float2 bb2 = __half22float2(*(__half2*)&rr.y);
        acc.x += w * aa.x; acc.y += w * aa.y; acc.z += w * bb2.x; acc.w += w * bb2.y;
    }
    float4 bb = *(const float4*)(bias + c);
    float4 o;
    o.x = tanhf(acc.x + bb.x);
    o.y = tanhf(acc.y + bb.y);
    o.z = tanhf(acc.z + bb.z);
    o.w = tanhf(acc.w + bb.w);
    *(float4*)(Hout + (size_t)gw * HD + c) = o;
}

// ---------------- readout ----------------------------------------------------
__global__ void k_readout(const float* __restrict__ Hl) {
    int g = blockIdx.x;
    int c = threadIdx.x;
    int s = g_gs[g], e = g_ge[g];
    float vmax = -INFINITY, vsum = 0.0f;
    for (int i = s; i < e; i++) {
        float v = Hl[(size_t)i * HD + c];
        vmax = fmaxf(vmax, v);
        vsum += v;
    }
    int cnt = e - s;
    g_hidden[(size_t)g * 256 + c] = (cnt > 0) ? vmax : 0.0f;
    g_hidden[(size_t)g * 256 + 128 + c] = vsum / fmaxf((float)cnt, 1.0f);
}

__global__ void k_final(const float* __restrict__ Wout, const float* __restrict__ bout) {
    __shared__ float red[256];
    int g = blockIdx.x, t = threadIdx.x;
    red[t] = g_hidden[(size_t)g * 256 + t] * Wout[t];
    __syncthreads();
    for (int off = 128; off > 0; off >>= 1) {
        if (t < off) red[t] += red[t + off];
        __syncthreads();
    }
    if (t == 0) g_out[g] = red[0] + bout[0];
}

// ---------------- emit -------------------------------------------------------
__global__ void k_emit(float* __restrict__ out, int out_size) {
    int i = blockIdx.x * blockDim.x + threadIdx.x;
    if (i >= out_size) return;
    float v;
    if (out_size >= NG + HID) {
        v = (i < NG) ? g_out[i] : g_hidden[i - NG];
    } else if (out_size == HID) {
        v = g_hidden[i];
    } else {
        v = (i < NG) ? g_out[i] : 0.0f;
    }
    out[i] = v;
}

// ---------------- launch -----------------------------------------------------
extern "C" void kernel_launch(void* const* d_in, const int* in_sizes, int n_in,
                              void* d_out, int out_size) {
    const float* x     = (const float*)d_in[0];
    const int*   ei    = (const int*)d_in[1];
    const int*   batch = (const int*)d_in[2];
    const float* ew    = (const float*)d_in[3];
    const float* W[4] = { (const float*)d_in[4], (const float*)d_in[6],
                          (const float*)d_in[8], (const float*)d_in[10] };
    const float* B[4] = { (const float*)d_in[5], (const float*)d_in[7],
                          (const float*)d_in[9], (const float*)d_in[11] };
    const float* Wout = (const float*)d_in[12];
    const float* bout = (const float*)d_in[13];

    cudaFuncSetAttribute(k_gemm, cudaFuncAttributeMaxDynamicSharedMemorySize, GEMM_SMEM);

    __half *tbuf, *wt;
    float *hA, *hB;
    cudaGetSymbolAddress((void**)&tbuf, g_t);
    cudaGetSymbolAddress((void**)&wt, g_wt);
    cudaGetSymbolAddress((void**)&hA, g_hA);
    cudaGetSymbolAddress((void**)&hB, g_hB);

    k_init<<<(NN + 255) / 256, 256>>>();
    k_deg<<<(NE + 255) / 256, 256>>>(ei, ew);
    k_bsum<<<NBLK, SCAN_B>>>();
    k_bscan<<<1, SCAN_B>>>();
    k_ptr<<<NBLK, SCAN_B>>>(batch);
    k_scatter<<<(NE + 255) / 256, 256>>>(ei, ew);
    k_wt<<<64, 256>>>(W[0], W[1], W[2], W[3]);

    const int gemm_grid = (NN + 127) / 128;
    const int aggr_grid = (NN * 32 + 255) / 256;

    const float* cur = x;
    float* ping[4] = { hA, hB, hA, hB };
    for (int l = 0; l < 4; l++) {
        k_gemm<<<gemm_grid, 256, GEMM_SMEM>>>(cur, wt + l * 16384, tbuf, NN);
        k_aggr<<<aggr_grid, 256>>>(tbuf, B[l], ping[l]);
        cur = ping[l];
    }

    k_readout<<<NG, 128>>>(cur);
    k_final<<<NG, 256>>>(Wout, bout);
    k_emit<<<(out_size + 255) / 256, 256>>>((float*)d_out, out_size);
}

// round 11
// speedup vs baseline: 2.2705x; 1.0218x over previous
#include <cuda_runtime.h>
#include <cuda_fp16.h>
#include <math.h>

#define NN 50000
#define NE 600000
#define HD 128
#define NG 64
#define HID (NG * 256)
#define SCAN_B 256
#define NBLK ((NN + SCAN_B - 1) / SCAN_B)   // 196

// ---------------- scratch ----------------------------------------------------
__device__ __align__(16) float g_deg[NN];
__device__ __align__(16) float g_self[NN];
__device__ __align__(16) int   g_cnt[NN];
__device__ __align__(16) int   g_ptr[NN + 1];
__device__ __align__(16) int   g_cur[NN];
__device__ __align__(16) int   g_bsum[NBLK];
__device__ __align__(16) int   g_boff[NBLK];
__device__ __align__(16) int   g_srcA[NE];
__device__ __align__(16) float g_normA[NE];
__device__ __align__(16) __half g_wt[4 * 128 * 128];   // W^T per layer, half [n][k]
__device__ __align__(16) __half g_t[(size_t)NN * HD];
__device__ __align__(16) float g_hA[(size_t)NN * HD];
__device__ __align__(16) float g_hB[(size_t)NN * HD];
__device__ __align__(16) float g_hidden[HID];
__device__ __align__(16) float g_out[NG];
__device__ int g_gs[NG], g_ge[NG];

// ---------------- setup kernels ---------------------------------------------
__global__ void k_init() {
    int i = blockIdx.x * blockDim.x + threadIdx.x;
    if (i < NN) { g_deg[i] = 2.0f; g_cnt[i] = 0; }
    if (i < NG) { g_gs[i] = 0; g_ge[i] = 0; }
}

__global__ void k_deg(const int* __restrict__ ei, const float* __restrict__ ew) {
    int i = blockIdx.x * blockDim.x + threadIdx.x;
    if (i >= NE) return;
    int d = ei[NE + i];
    if ((unsigned)d >= NN) return;
    atomicAdd(&g_deg[d], ew[i]);
    atomicAdd(&g_cnt[d], 1);
}

__global__ void k_bsum() {
    __shared__ int sh[SCAN_B];
    int i = blockIdx.x * SCAN_B + threadIdx.x;
    if (i < NN) {
        float dv = rsqrtf(g_deg[i]);
        g_deg[i] = dv;
        g_self[i] = 2.0f * dv * dv;
    }
    sh[threadIdx.x] = (i < NN) ? g_cnt[i] : 0;
    __syncthreads();
    for (int off = SCAN_B / 2; off > 0; off >>= 1) {
        if (threadIdx.x < off) sh[threadIdx.x] += sh[threadIdx.x + off];
        __syncthreads();
    }
    if (threadIdx.x == 0) g_bsum[blockIdx.x] = sh[0];
}

__global__ void k_bscan() {
    __shared__ int wsum[8];
    int t = threadIdx.x;
    int v = (t < NBLK) ? g_bsum[t] : 0;
    int x = v;
#pragma unroll
    for (int o = 1; o < 32; o <<= 1) {
        int y = __shfl_up_sync(0xffffffffu, x, o);
        if ((t & 31) >= o) x += y;
    }
    if ((t & 31) == 31) wsum[t >> 5] = x;
    __syncthreads();
    if (t < 8) {
        int y = wsum[t];
#pragma unroll
        for (int o = 1; o < 8; o <<= 1) {
            int z = __shfl_up_sync(0xffu, y, o);
            if (t >= o) y += z;
        }
        wsum[t] = y;
    }
    __syncthreads();
    int base = (t >= 32) ? wsum[(t >> 5) - 1] : 0;
    int inc = base + x;
    if (t < NBLK) g_boff[t] = inc - v;
    if (t == NBLK - 1) g_ptr[NN] = inc;
}

__global__ void k_ptr(const int* __restrict__ batch) {
    __shared__ int wsum[8];
    int i = blockIdx.x * SCAN_B + threadIdx.x;
    int t = threadIdx.x;
    int v = (i < NN) ? g_cnt[i] : 0;
    int x = v;
#pragma unroll
    for (int o = 1; o < 32; o <<= 1) {
        int y = __shfl_up_sync(0xffffffffu, x, o);
        if ((t & 31) >= o) x += y;
    }
    if ((t & 31) == 31) wsum[t >> 5] = x;
    __syncthreads();
    if (t < 8) {
        int y = wsum[t];
#pragma unroll
        for (int o = 1; o < 8; o <<= 1) {
            int z = __shfl_up_sync(0xffu, y, o);
            if (t >= o) y += z;
        }
        wsum[t] = y;
    }
    __syncthreads();
    int base = (t >= 32) ? wsum[(t >> 5) - 1] : 0;
    if (i < NN) {
        int p = g_boff[blockIdx.x] + base + x - v;
        g_ptr[i] = p;
        g_cur[i] = p;
        int g = batch[i];
        if ((unsigned)g < NG) {
            if (i == 0 || batch[i - 1] != g) g_gs[g] = i;
            if (i == NN - 1 || batch[i + 1] != g) g_ge[g] = i + 1;
        }
    }
}

__global__ void k_scatter(const int* __restrict__ ei, const float* __restrict__ ew) {
    int i = blockIdx.x * blockDim.x + threadIdx.x;
    if (i >= NE) return;
    int s = ei[i];
    int d = ei[NE + i];
    if ((unsigned)s >= NN || (unsigned)d >= NN) return;
    int pos = atomicAdd(&g_cur[d], 1);
    if ((unsigned)pos >= NE) return;
    g_srcA[pos] = s;
    g_normA[pos] = g_deg[s] * ew[i] * g_deg[d];
}

// transpose + convert all 4 weight matrices to half [n][k]
__global__ void k_wt(const float* __restrict__ W0, const float* __restrict__ W1,
                     const float* __restrict__ W2, const float* __restrict__ W3) {
    int idx = blockIdx.x * blockDim.x + threadIdx.x;
    if (idx >= 128 * 128) return;
    int k = idx >> 7, n = idx & 127;
    g_wt[0 * 16384 + n * 128 + k] = __float2half(W0[idx]);
    g_wt[1 * 16384 + n * 128 + k] = __float2half(W1[idx]);
    g_wt[2 * 16384 + n * 128 + k] = __float2half(W2[idx]);
    g_wt[3 * 16384 + n * 128 + k] = __float2half(W3[idx]);
}

// ---------------- FP16 tensor-core GEMM: O[n,128] = A @ W, fp32 accum -------
#define SK 136
#define GEMM_SMEM (2 * 128 * SK * (int)sizeof(__half))

__device__ __forceinline__ void mma_f16(float* c, unsigned a0, unsigned a1,
                                        unsigned a2, unsigned a3,
                                        unsigned b0, unsigned b1) {
    asm volatile(
        "mma.sync.aligned.m16n8k16.row.col.f32.f16.f16.f32 "
        "{%0,%1,%2,%3}, {%4,%5,%6,%7}, {%8,%9}, {%0,%1,%2,%3};"
        : "+f"(c[0]), "+f"(c[1]), "+f"(c[2]), "+f"(c[3])
        : "r"(a0), "r"(a1), "r"(a2), "r"(a3), "r"(b0), "r"(b1));
}

__global__ __launch_bounds__(256) void k_gemm(const float* __restrict__ A,
                                              const __half* __restrict__ Wt,
                                              __half* __restrict__ O, int nrows) {
    extern __shared__ __half smh[];
    __half* Wn = smh;            // [n][SK]
    __half* As = smh + 128 * SK; // [r][SK]
    const int tid = threadIdx.x;
    const int row0 = blockIdx.x * 128;

#pragma unroll
    for (int i = 0; i < 8; i++) {
        int u = tid + i * 256;
        int n = u >> 4, kq = u & 15;
        *(uint4*)(Wn + n * SK + kq * 8) = *(const uint4*)(Wt + n * 128 + kq * 8);
    }
#pragma unroll
    for (int i = 0; i < 8; i++) {
        int u = tid + i * 256;
        int r = u >> 4, kq = u & 15;
        int gr = row0 + r;
        float4 v0, v1;
        if (gr < nrows) {
            v0 = *(const float4*)(A + (size_t)gr * HD + kq * 8);
            v1 = *(const float4*)(A + (size_t)gr * HD + kq * 8 + 4);
        } else {
            v0 = make_float4(0.f, 0.f, 0.f, 0.f);
            v1 = v0;
        }
        __half2 h[4];
        h[0] = __floats2half2_rn(v0.x, v0.y);
        h[1] = __floats2half2_rn(v0.z, v0.w);
        h[2] = __floats2half2_rn(v1.x, v1.y);
        h[3] = __floats2half2_rn(v1.z, v1.w);
        *(uint4*)(As + r * SK + kq * 8) = *(uint4*)h;
    }
    __syncthreads();

    const int wid = tid >> 5, lane = tid & 31;
    const int r = lane >> 2;
    const int q = lane & 3;
    const int warpRow = wid * 16;

    float acc[16][4];
#pragma unroll
    for (int nt = 0; nt < 16; nt++) {
        acc[nt][0] = 0.f; acc[nt][1] = 0.f; acc[nt][2] = 0.f; acc[nt][3] = 0.f;
    }

#pragma unroll
    for (int k0 = 0; k0 < 128; k0 += 16) {
        unsigned a0 = *(const unsigned*)(As + (warpRow + r) * SK + k0 + q * 2);
        unsigned a1 = *(const unsigned*)(As + (warpRow + r + 8) * SK + k0 + q * 2);
        unsigned a2 = *(const unsigned*)(As + (warpRow + r) * SK + k0 + q * 2 + 8);
        unsigned a3 = *(const unsigned*)(As + (warpRow + r + 8) * SK + k0 + q * 2 + 8);
#pragma unroll
        for (int nt = 0; nt < 16; nt++) {
            int n0 = nt * 8;
            unsigned b0 = *(const unsigned*)(Wn + (n0 + r) * SK + k0 + q * 2);
            unsigned b1 = *(const unsigned*)(Wn + (n0 + r) * SK + k0 + q * 2 + 8);
            mma_f16(acc[nt], a0, a1, a2, a3, b0, b1);
        }
    }

    int orowA = row0 + warpRow + r;
    int orowB = orowA + 8;
#pragma unroll
    for (int nt = 0; nt < 16; nt++) {
        int n = nt * 8 + q * 2;
        if (orowA < nrows)
            *(__half2*)(O + (size_t)orowA * HD + n) =
                __floats2half2_rn(acc[nt][0], acc[nt][1]);
        if (orowB < nrows)
            *(__half2*)(O + (size_t)orowB * HD + n) =
                __floats2half2_rn(acc[nt][2], acc[nt][3]);
    }
}

// ---------------- aggregation: one warp per destination, 64-thr blocks ------
__global__ __launch_bounds__(64) void k_aggr(const __half* __restrict__ T,
                                             const float* __restrict__ bias,
                                             float* __restrict__ Hout) {
    int gw = (blockIdx.x * blockDim.x + threadIdx.x) >> 5;
    if (gw >= NN) return;
    const int lane = threadIdx.x & 31;
    const int c = lane << 2;

    float sn = g_self[gw];
    uint2 tr = *(const uint2*)(T + (size_t)gw * HD + c);
    float2 ta = __half22float2(*(__half2*)&tr.x);
    float2 tb = __half22float2(*(__half2*)&tr.y);
    float4 acc = make_float4(ta.x * sn, ta.y * sn, tb.x * sn, tb.y * sn);

    int e = g_ptr[gw];
    const int e1 = g_ptr[gw + 1];
    for (; e + 3 < e1; e += 4) {
        int s0 = g_srcA[e], s1 = g_srcA[e + 1], s2 = g_srcA[e + 2], s3 = g_srcA[e + 3];
        float w0 = g_normA[e], w1 = g_normA[e + 1], w2 = g_normA[e + 2], w3 = g_normA[e + 3];
        uint2 r0 = *(const uint2*)(T + (size_t)s0 * HD + c);
        uint2 r1 = *(const uint2*)(T + (size_t)s1 * HD + c);
        uint2 r2 = *(const uint2*)(T + (size_t)s2 * HD + c);
        uint2 r3 = *(const uint2*)(T + (size_t)s3 * HD + c);
        float2 a0 = __half22float2(*(__half2*)&r0.x), b0 = __half22float2(*(__half2*)&r0.y);
        float2 a1 = __half22float2(*(__half2*)&r1.x), b1 = __half22float2(*(__half2*)&r1.y);
        float2 a2 = __half22float2(*(__half2*)&r2.x), b2 = __half22float2(*(__half2*)&r2.y);
        float2 a3 = __half22float2(*(__half2*)&r3.x), b3 = __half22float2(*(__half2*)&r3.y);
        acc.x += w0 * a0.x + w1 * a1.x + w2 * a2.x + w3 * a3.x;
        acc.y += w0 * a0.y + w1 * a1.y + w2 * a2.y + w3 * a3.y;
        acc.z += w0 * b0.x + w1 * b1.x + w2 * b2.x + w3 * b3.x;
        acc.w += w0 * b0.y + w1 * b1.y + w2 * b2.y + w3 * b3.y;
    }
    for (; e < e1; e++) {
        int s = g_srcA[e];
        float w = g_normA[e];
        uint2 rr = *(const uint2*)(T + (size_t)s * HD + c);
        float2 aa = __half22float2(*(__half2*)&rr.x);
        float2 bb2 = __half22float2(*(__half2*)&rr.y);
        acc.x += w * aa.x; acc.y += w * aa.y; acc.z += w * bb2.x; acc.w += w * bb2.y;
    }
    float4 bb = *(const float4*)(bias + c);
    float4 o;
    o.x = tanhf(acc.x + bb.x);
    o.y = tanhf(acc.y + bb.y);
    o.z = tanhf(acc.z + bb.z);
    o.w = tanhf(acc.w + bb.w);
    *(float4*)(Hout + (size_t)gw * HD + c) = o;
}

// ---------------- readout ----------------------------------------------------
__global__ void k_readout(const float* __restrict__ Hl) {
    int g = blockIdx.x;
    int c = threadIdx.x;
    int s = g_gs[g], e = g_ge[g];
    float vmax = -INFINITY, vsum = 0.0f;
    for (int i = s; i < e; i++) {
        float v = Hl[(size_t)i * HD + c];
        vmax = fmaxf(vmax, v);
        vsum += v;
    }
    int cnt = e - s;
    g_hidden[(size_t)g * 256 + c] = (cnt > 0) ? vmax : 0.0f;
    g_hidden[(size_t)g * 256 + 128 + c] = vsum / fmaxf((float)cnt, 1.0f);
}

__global__ void k_final(const float* __restrict__ Wout, const float* __restrict__ bout) {
    __shared__ float red[256];
    int g = blockIdx.x, t = threadIdx.x;
    red[t] = g_hidden[(size_t)g * 256 + t] * Wout[t];
    __syncthreads();
    for (int off = 128; off > 0; off >>= 1) {
        if (t < off) red[t] += red[t + off];
        __syncthreads();
    }
    if (t == 0) g_out[g] = red[0] + bout[0];
}

// ---------------- emit -------------------------------------------------------
__global__ void k_emit(float* __restrict__ out, int out_size) {
    int i = blockIdx.x * blockDim.x + threadIdx.x;
    if (i >= out_size) return;
    float v;
    if (out_size >= NG + HID) {
        v = (i < NG) ? g_out[i] : g_hidden[i - NG];
    } else if (out_size == HID) {
        v = g_hidden[i];
    } else {
        v = (i < NG) ? g_out[i] : 0.0f;
    }
    out[i] = v;
}

// ---------------- launch -----------------------------------------------------
extern "C" void kernel_launch(void* const* d_in, const int* in_sizes, int n_in,
                              void* d_out, int out_size) {
    const float* x     = (const float*)d_in[0];
    const int*   ei    = (const int*)d_in[1];
    const int*   batch = (const int*)d_in[2];
    const float* ew    = (const float*)d_in[3];
    const float* W[4] = { (const float*)d_in[4], (const float*)d_in[6],
                          (const float*)d_in[8], (const float*)d_in[10] };
    const float* B[4] = { (const float*)d_in[5], (const float*)d_in[7],
                          (const float*)d_in[9], (const float*)d_in[11] };
    const float* Wout = (const float*)d_in[12];
    const float* bout = (const float*)d_in[13];

    cudaFuncSetAttribute(k_gemm, cudaFuncAttributeMaxDynamicSharedMemorySize, GEMM_SMEM);

    __half *tbuf, *wt;
    float *hA, *hB;
    cudaGetSymbolAddress((void**)&tbuf, g_t);
    cudaGetSymbolAddress((void**)&wt, g_wt);
    cudaGetSymbolAddress((void**)&hA, g_hA);
    cudaGetSymbolAddress((void**)&hB, g_hB);

    const int gemm_grid = (NN + 127) / 128;
    const int aggr_grid = (NN * 32 + 63) / 64;

    // Reordered: gemm for layer 0 is launch #3 (only needs x + wt) so the
    // profiler's fixed sampling window captures it.
    k_init<<<(NN + 255) / 256, 256>>>();                       // 0
    k_deg<<<(NE + 255) / 256, 256>>>(ei, ew);                  // 1
    k_wt<<<64, 256>>>(W[0], W[1], W[2], W[3]);                 // 2
    k_gemm<<<gemm_grid, 256, GEMM_SMEM>>>(x, wt, tbuf, NN);    // 3 <- profiled
    k_bsum<<<NBLK, SCAN_B>>>();                                // 4
    k_bscan<<<1, SCAN_B>>>();                                  // 5
    k_ptr<<<NBLK, SCAN_B>>>(batch);                            // 6
    k_scatter<<<(NE + 255) / 256, 256>>>(ei, ew);              // 7

    float* ping[4] = { hA, hB, hA, hB };
    k_aggr<<<aggr_grid, 64>>>(tbuf, B[0], ping[0]);
    const float* cur = ping[0];
    for (int l = 1; l < 4; l++) {
        k_gemm<<<gemm_grid, 256, GEMM_SMEM>>>(cur, wt + l * 16384, tbuf, NN);
        k_aggr<<<aggr_grid, 64>>>(tbuf, B[l], ping[l]);
        cur = ping[l];
    }

    k_readout<<<NG, 128>>>(cur);
    k_final<<<NG, 256>>>(Wout, bout);
    k_emit<<<(out_size + 255) / 256, 256>>>((float*)d_out, out_size);
}

// round 12
// speedup vs baseline: 2.3546x; 1.0370x over previous
#include <cuda_runtime.h>
#include <cuda_fp16.h>
#include <math.h>

#define NN 50000
#define NE 600000
#define HD 128
#define NG 64
#define HID (NG * 256)
#define SCAN_B 256
#define NBLK ((NN + SCAN_B - 1) / SCAN_B)   // 196

// ---------------- scratch ----------------------------------------------------
__device__ __align__(16) float g_deg[NN];
__device__ __align__(16) float g_self[NN];
__device__ __align__(16) int   g_cnt[NN];
__device__ __align__(16) int   g_ptr[NN + 1];
__device__ __align__(16) int   g_cur[NN];
__device__ __align__(16) int   g_bsum[NBLK];
__device__ __align__(16) int   g_boff[NBLK];
__device__ __align__(16) int   g_srcA[NE];
__device__ __align__(16) float g_normA[NE];
__device__ __align__(16) __half g_wt[4 * 128 * 128];   // W^T per layer [n][k]
__device__ __align__(16) __half g_t[(size_t)NN * HD];  // GEMM out (gathered)
__device__ __align__(16) __half g_hA[(size_t)NN * HD]; // activations ping
__device__ __align__(16) __half g_hB[(size_t)NN * HD]; // activations pong (x16 first)
__device__ __align__(16) float g_hidden[HID];
__device__ __align__(16) float g_out[NG];
__device__ int g_gs[NG], g_ge[NG];

// ---------------- setup kernels ---------------------------------------------
__global__ void k_init() {
    int i = blockIdx.x * blockDim.x + threadIdx.x;
    if (i < NN) { g_deg[i] = 2.0f; g_cnt[i] = 0; }
    if (i < NG) { g_gs[i] = 0; g_ge[i] = 0; }
}

// x fp32 -> fp16 (8 elems/thread)
__global__ void k_x2h(const float* __restrict__ x, __half* __restrict__ o) {
    int i = blockIdx.x * blockDim.x + threadIdx.x;
    if (i >= NN * HD / 8) return;
    float4 v0 = ((const float4*)x)[2 * i];
    float4 v1 = ((const float4*)x)[2 * i + 1];
    __half2 h[4];
    h[0] = __floats2half2_rn(v0.x, v0.y);
    h[1] = __floats2half2_rn(v0.z, v0.w);
    h[2] = __floats2half2_rn(v1.x, v1.y);
    h[3] = __floats2half2_rn(v1.z, v1.w);
    ((uint4*)o)[i] = *(uint4*)h;
}

__global__ void k_deg(const int* __restrict__ ei, const float* __restrict__ ew) {
    int i = blockIdx.x * blockDim.x + threadIdx.x;
    if (i >= NE) return;
    int d = ei[NE + i];
    if ((unsigned)d >= NN) return;
    atomicAdd(&g_deg[d], ew[i]);
    atomicAdd(&g_cnt[d], 1);
}

__global__ void k_bsum() {
    __shared__ int sh[SCAN_B];
    int i = blockIdx.x * SCAN_B + threadIdx.x;
    if (i < NN) {
        float dv = rsqrtf(g_deg[i]);
        g_deg[i] = dv;
        g_self[i] = 2.0f * dv * dv;
    }
    sh[threadIdx.x] = (i < NN) ? g_cnt[i] : 0;
    __syncthreads();
    for (int off = SCAN_B / 2; off > 0; off >>= 1) {
        if (threadIdx.x < off) sh[threadIdx.x] += sh[threadIdx.x + off];
        __syncthreads();
    }
    if (threadIdx.x == 0) g_bsum[blockIdx.x] = sh[0];
}

__global__ void k_bscan() {
    __shared__ int wsum[8];
    int t = threadIdx.x;
    int v = (t < NBLK) ? g_bsum[t] : 0;
    int x = v;
#pragma unroll
    for (int o = 1; o < 32; o <<= 1) {
        int y = __shfl_up_sync(0xffffffffu, x, o);
        if ((t & 31) >= o) x += y;
    }
    if ((t & 31) == 31) wsum[t >> 5] = x;
    __syncthreads();
    if (t < 8) {
        int y = wsum[t];
#pragma unroll
        for (int o = 1; o < 8; o <<= 1) {
            int z = __shfl_up_sync(0xffu, y, o);
            if (t >= o) y += z;
        }
        wsum[t] = y;
    }
    __syncthreads();
    int base = (t >= 32) ? wsum[(t >> 5) - 1] : 0;
    int inc = base + x;
    if (t < NBLK) g_boff[t] = inc - v;
    if (t == NBLK - 1) g_ptr[NN] = inc;
}

__global__ void k_ptr(const int* __restrict__ batch) {
    __shared__ int wsum[8];
    int i = blockIdx.x * SCAN_B + threadIdx.x;
    int t = threadIdx.x;
    int v = (i < NN) ? g_cnt[i] : 0;
    int x = v;
#pragma unroll
    for (int o = 1; o < 32; o <<= 1) {
        int y = __shfl_up_sync(0xffffffffu, x, o);
        if ((t & 31) >= o) x += y;
    }
    if ((t & 31) == 31) wsum[t >> 5] = x;
    __syncthreads();
    if (t < 8) {
        int y = wsum[t];
#pragma unroll
        for (int o = 1; o < 8; o <<= 1) {
            int z = __shfl_up_sync(0xffu, y, o);
            if (t >= o) y += z;
        }
        wsum[t] = y;
    }
    __syncthreads();
    int base = (t >= 32) ? wsum[(t >> 5) - 1] : 0;
    if (i < NN) {
        int p = g_boff[blockIdx.x] + base + x - v;
        g_ptr[i] = p;
        g_cur[i] = p;
        int g = batch[i];
        if ((unsigned)g < NG) {
            if (i == 0 || batch[i - 1] != g) g_gs[g] = i;
            if (i == NN - 1 || batch[i + 1] != g) g_ge[g] = i + 1;
        }
    }
}

__global__ void k_scatter(const int* __restrict__ ei, const float* __restrict__ ew) {
    int i = blockIdx.x * blockDim.x + threadIdx.x;
    if (i >= NE) return;
    int s = ei[i];
    int d = ei[NE + i];
    if ((unsigned)s >= NN || (unsigned)d >= NN) return;
    int pos = atomicAdd(&g_cur[d], 1);
    if ((unsigned)pos >= NE) return;
    g_srcA[pos] = s;
    g_normA[pos] = g_deg[s] * ew[i] * g_deg[d];
}

__global__ void k_wt(const float* __restrict__ W0, const float* __restrict__ W1,
                     const float* __restrict__ W2, const float* __restrict__ W3) {
    int idx = blockIdx.x * blockDim.x + threadIdx.x;
    if (idx >= 128 * 128) return;
    int k = idx >> 7, n = idx & 127;
    g_wt[0 * 16384 + n * 128 + k] = __float2half(W0[idx]);
    g_wt[1 * 16384 + n * 128 + k] = __float2half(W1[idx]);
    g_wt[2 * 16384 + n * 128 + k] = __float2half(W2[idx]);
    g_wt[3 * 16384 + n * 128 + k] = __float2half(W3[idx]);
}

// ---------------- FP16 HMMA GEMM with ldmatrix fragment loads ----------------
#define SK 136
#define GEMM_SMEM (2 * 128 * SK * (int)sizeof(__half))

__device__ __forceinline__ void mma_f16(float* c, unsigned a0, unsigned a1,
                                        unsigned a2, unsigned a3,
                                        unsigned b0, unsigned b1) {
    asm volatile(
        "mma.sync.aligned.m16n8k16.row.col.f32.f16.f16.f32 "
        "{%0,%1,%2,%3}, {%4,%5,%6,%7}, {%8,%9}, {%0,%1,%2,%3};"
        : "+f"(c[0]), "+f"(c[1]), "+f"(c[2]), "+f"(c[3])
        : "r"(a0), "r"(a1), "r"(a2), "r"(a3), "r"(b0), "r"(b1));
}

__device__ __forceinline__ void ldsm_x4(unsigned* r, unsigned addr) {
    asm volatile(
        "ldmatrix.sync.aligned.m8n8.x4.shared.b16 {%0,%1,%2,%3}, [%4];"
        : "=r"(r[0]), "=r"(r[1]), "=r"(r[2]), "=r"(r[3]) : "r"(addr));
}

__global__ __launch_bounds__(256) void k_gemm(const __half* __restrict__ A,
                                              const __half* __restrict__ Wt,
                                              __half* __restrict__ O, int nrows) {
    extern __shared__ __half smh[];
    __half* Wn = smh;            // [n][SK]
    __half* As = smh + 128 * SK; // [r][SK]
    const int tid = threadIdx.x;
    const int row0 = blockIdx.x * 128;

    // Wn fill: vector copy
#pragma unroll
    for (int i = 0; i < 8; i++) {
        int u = tid + i * 256;
        int n = u >> 4, kq = u & 15;
        *(uint4*)(Wn + n * SK + kq * 8) = *(const uint4*)(Wt + n * 128 + kq * 8);
    }
    // As fill: vector copy (A already fp16), zero-pad tail rows
#pragma unroll
    for (int i = 0; i < 8; i++) {
        int u = tid + i * 256;
        int r = u >> 4, kq = u & 15;
        int gr = row0 + r;
        uint4 v = (gr < nrows) ? *(const uint4*)(A + (size_t)gr * HD + kq * 8)
                               : make_uint4(0u, 0u, 0u, 0u);
        *(uint4*)(As + r * SK + kq * 8) = v;
    }
    __syncthreads();

    const int wid = tid >> 5, lane = tid & 31;
    const int r = lane >> 2;
    const int q = lane & 3;
    const int warpRow = wid * 16;

    // ldmatrix lane address bases (generic->shared)
    // A x4: lane -> row warpRow+(lane&15), col offset ((lane&16)?8:0)
    unsigned aBase = (unsigned)__cvta_generic_to_shared(
        As + (warpRow + (lane & 15)) * SK + ((lane & 16) ? 8 : 0));
    // B x4 (covers 2 k-steps): lane -> row n=(lane&7), col offset 8*(lane>>3)
    unsigned bBase = (unsigned)__cvta_generic_to_shared(
        Wn + (lane & 7) * SK + ((lane >> 3) << 3));

    float acc[16][4];
#pragma unroll
    for (int nt = 0; nt < 16; nt++) {
        acc[nt][0] = 0.f; acc[nt][1] = 0.f; acc[nt][2] = 0.f; acc[nt][3] = 0.f;
    }

#pragma unroll
    for (int k0 = 0; k0 < 128; k0 += 32) {
        unsigned a[8];
        ldsm_x4(a, aBase + k0 * 2);             // k-step k0
        ldsm_x4(a + 4, aBase + (k0 + 16) * 2);  // k-step k0+16
#pragma unroll
        for (int nt = 0; nt < 16; nt++) {
            unsigned b[4];
            ldsm_x4(b, bBase + (nt * 8 * SK + k0) * 2);
            mma_f16(acc[nt], a[0], a[1], a[2], a[3], b[0], b[1]);
            mma_f16(acc[nt], a[4], a[5], a[6], a[7], b[2], b[3]);
        }
    }

    int orowA = row0 + warpRow + r;
    int orowB = orowA + 8;
#pragma unroll
    for (int nt = 0; nt < 16; nt++) {
        int n = nt * 8 + q * 2;
        if (orowA < nrows)
            *(__half2*)(O + (size_t)orowA * HD + n) =
                __floats2half2_rn(acc[nt][0], acc[nt][1]);
        if (orowB < nrows)
            *(__half2*)(O + (size_t)orowB * HD + n) =
                __floats2half2_rn(acc[nt][2], acc[nt][3]);
    }
}

// ---------------- aggregation: one warp per destination, fp16 in/out --------
__global__ __launch_bounds__(64) void k_aggr(const __half* __restrict__ T,
                                             const float* __restrict__ bias,
                                             __half* __restrict__ Hout) {
    int gw = (blockIdx.x * blockDim.x + threadIdx.x) >> 5;
    if (gw >= NN) return;
    const int lane = threadIdx.x & 31;
    const int c = lane << 2;

    float sn = g_self[gw];
    uint2 tr = *(const uint2*)(T + (size_t)gw * HD + c);
    float2 ta = __half22float2(*(__half2*)&tr.x);
    float2 tb = __half22float2(*(__half2*)&tr.y);
    float4 acc = make_float4(ta.x * sn, ta.y * sn, tb.x * sn, tb.y * sn);

    int e = g_ptr[gw];
    const int e1 = g_ptr[gw + 1];
    for (; e + 3 < e1; e += 4) {
        int s0 = g_srcA[e], s1 = g_srcA[e + 1], s2 = g_srcA[e + 2], s3 = g_srcA[e + 3];
        float w0 = g_normA[e], w1 = g_normA[e + 1], w2 = g_normA[e + 2], w3 = g_normA[e + 3];
        uint2 r0 = *(const uint2*)(T + (size_t)s0 * HD + c);
        uint2 r1 = *(const uint2*)(T + (size_t)s1 * HD + c);
        uint2 r2 = *(const uint2*)(T + (size_t)s2 * HD + c);
        uint2 r3 = *(const uint2*)(T + (size_t)s3 * HD + c);
        float2 a0 = __half22float2(*(__half2*)&r0.x), b0 = __half22float2(*(__half2*)&r0.y);
        float2 a1 = __half22float2(*(__half2*)&r1.x), b1 = __half22float2(*(__half2*)&r1.y);
        float2 a2 = __half22float2(*(__half2*)&r2.x), b2 = __half22float2(*(__half2*)&r2.y);
        float2 a3 = __half22float2(*(__half2*)&r3.x), b3 = __half22float2(*(__half2*)&r3.y);
        acc.x += w0 * a0.x + w1 * a1.x + w2 * a2.x + w3 * a3.x;
        acc.y += w0 * a0.y + w1 * a1.y + w2 * a2.y + w3 * a3.y;
        acc.z += w0 * b0.x + w1 * b1.x + w2 * b2.x + w3 * b3.x;
        acc.w += w0 * b0.y + w1 * b1.y + w2 * b2.y + w3 * b3.y;
    }
    for (; e < e1; e++) {
        int s = g_srcA[e];
        float w = g_normA[e];
        uint2 rr = *(const uint2*)(T + (size_t)s * HD + c);
        float2 aa = __half22float2(*(__half2*)&rr.x);
        float2 bb2 = __half22float2(*(__half2*)&rr.y);
        acc.x += w * aa.x; acc.y += w * aa.y; acc.z += w * bb2.x; acc.w += w * bb2.y;
    }
    float4 bb = *(const float4*)(bias + c);
    __half2 o[2];
    o[0] = __floats2half2_rn(tanhf(acc.x + bb.x), tanhf(acc.y + bb.y));
    o[1] = __floats2half2_rn(tanhf(acc.z + bb.z), tanhf(acc.w + bb.w));
    *(uint2*)(Hout + (size_t)gw * HD + c) = *(uint2*)o;
}

// ---------------- readout (fp16 input) ---------------------------------------
__global__ void k_readout(const __half* __restrict__ Hl) {
    int g = blockIdx.x;
    int c = threadIdx.x;
    int s = g_gs[g], e = g_ge[g];
    float vmax = -INFINITY, vsum = 0.0f;
    for (int i = s; i < e; i++) {
        float v = __half2float(Hl[(size_t)i * HD + c]);
        vmax = fmaxf(vmax, v);
        vsum += v;
    }
    int cnt = e - s;
    g_hidden[(size_t)g * 256 + c] = (cnt > 0) ? vmax : 0.0f;
    g_hidden[(size_t)g * 256 + 128 + c] = vsum / fmaxf((float)cnt, 1.0f);
}

__global__ void k_final(const float* __restrict__ Wout, const float* __restrict__ bout) {
    __shared__ float red[256];
    int g = blockIdx.x, t = threadIdx.x;
    red[t] = g_hidden[(size_t)g * 256 + t] * Wout[t];
    __syncthreads();
    for (int off = 128; off > 0; off >>= 1) {
        if (t < off) red[t] += red[t + off];
        __syncthreads();
    }
    if (t == 0) g_out[g] = red[0] + bout[0];
}

// ---------------- emit -------------------------------------------------------
__global__ void k_emit(float* __restrict__ out, int out_size) {
    int i = blockIdx.x * blockDim.x + threadIdx.x;
    if (i >= out_size) return;
    float v;
    if (out_size >= NG + HID) {
        v = (i < NG) ? g_out[i] : g_hidden[i - NG];
    } else if (out_size == HID) {
        v = g_hidden[i];
    } else {
        v = (i < NG) ? g_out[i] : 0.0f;
    }
    out[i] = v;
}

// ---------------- launch -----------------------------------------------------
extern "C" void kernel_launch(void* const* d_in, const int* in_sizes, int n_in,
                              void* d_out, int out_size) {
    const float* x     = (const float*)d_in[0];
    const int*   ei    = (const int*)d_in[1];
    const int*   batch = (const int*)d_in[2];
    const float* ew    = (const float*)d_in[3];
    const float* W[4] = { (const float*)d_in[4], (const float*)d_in[6],
                          (const float*)d_in[8], (const float*)d_in[10] };
    const float* B[4] = { (const float*)d_in[5], (const float*)d_in[7],
                          (const float*)d_in[9], (const float*)d_in[11] };
    const float* Wout = (const float*)d_in[12];
    const float* bout = (const float*)d_in[13];

    cudaFuncSetAttribute(k_gemm, cudaFuncAttributeMaxDynamicSharedMemorySize, GEMM_SMEM);

    __half *tbuf, *wt, *hA, *hB;
    cudaGetSymbolAddress((void**)&tbuf, g_t);
    cudaGetSymbolAddress((void**)&wt, g_wt);
    cudaGetSymbolAddress((void**)&hA, g_hA);
    cudaGetSymbolAddress((void**)&hB, g_hB);

    const int gemm_grid = (NN + 127) / 128;
    const int aggr_grid = (NN * 32 + 63) / 64;

    k_init<<<(NN + 255) / 256, 256>>>();                        // 0
    k_x2h<<<(NN * HD / 8 + 255) / 256, 256>>>(x, hB);           // 1
    k_wt<<<64, 256>>>(W[0], W[1], W[2], W[3]);                  // 2
    k_gemm<<<gemm_grid, 256, GEMM_SMEM>>>(hB, wt, tbuf, NN);    // 3 <- profiled
    k_deg<<<(NE + 255) / 256, 256>>>(ei, ew);                   // 4
    k_bsum<<<NBLK, SCAN_B>>>();                                 // 5
    k_bscan<<<1, SCAN_B>>>();                                   // 6
    k_ptr<<<NBLK, SCAN_B>>>(batch);                             // 7
    k_scatter<<<(NE + 255) / 256, 256>>>(ei, ew);               // 8

    __half* ping[4] = { hA, hB, hA, hB };
    k_aggr<<<aggr_grid, 64>>>(tbuf, B[0], ping[0]);
    const __half* cur = ping[0];
    for (int l = 1; l < 4; l++) {
        k_gemm<<<gemm_grid, 256, GEMM_SMEM>>>(cur, wt + l * 16384, tbuf, NN);
        k_aggr<<<aggr_grid, 64>>>(tbuf, B[l], ping[l]);
        cur = ping[l];
    }

    k_readout<<<NG, 128>>>(cur);
    k_final<<<NG, 256>>>(Wout, bout);
    k_emit<<<(out_size + 255) / 256, 256>>>((float*)d_out, out_size);
}

// round 13
// speedup vs baseline: 2.4600x; 1.0447x over previous
#include <cuda_runtime.h>
#include <cuda_fp16.h>
#include <math.h>

#define NN 50000
#define NE 600000
#define HD 128
#define NG 64
#define HID (NG * 256)
#define SCAN_B 256
#define NBLK ((NN + SCAN_B - 1) / SCAN_B)   // 196

// ---------------- scratch ----------------------------------------------------
__device__ __align__(16) float g_deg[NN];
__device__ __align__(16) float g_self[NN];
__device__ __align__(16) int   g_cnt[NN];
__device__ __align__(16) int   g_ptr[NN + 1];
__device__ __align__(16) int   g_cur[NN];
__device__ __align__(16) int   g_bsum[NBLK];
__device__ __align__(16) int   g_srcA[NE];
__device__ __align__(16) float g_normA[NE];
__device__ __align__(16) __half g_wt[4 * 128 * 128];   // W^T per layer [n][k]
__device__ __align__(16) __half g_t[(size_t)NN * HD];
__device__ __align__(16) __half g_hA[(size_t)NN * HD];
__device__ __align__(16) __half g_hB[(size_t)NN * HD];
__device__ __align__(16) float g_hidden[HID];
__device__ __align__(16) float g_out[NG];
__device__ int g_gs[NG], g_ge[NG];

// ---------------- fused setup: init + x->fp16 + W transpose -----------------
__global__ void k_setup(const float* __restrict__ x, __half* __restrict__ xo,
                        const float* __restrict__ W0, const float* __restrict__ W1,
                        const float* __restrict__ W2, const float* __restrict__ W3) {
    int j = blockIdx.x * blockDim.x + threadIdx.x;
    if (j < NN * HD / 8) {
        float4 v0 = ((const float4*)x)[2 * j];
        float4 v1 = ((const float4*)x)[2 * j + 1];
        __half2 h[4];
        h[0] = __floats2half2_rn(v0.x, v0.y);
        h[1] = __floats2half2_rn(v0.z, v0.w);
        h[2] = __floats2half2_rn(v1.x, v1.y);
        h[3] = __floats2half2_rn(v1.z, v1.w);
        ((uint4*)xo)[j] = *(uint4*)h;
    }
    if (j < NN) { g_deg[j] = 2.0f; g_cnt[j] = 0; }
    if (j < NG) { g_gs[j] = 0; g_ge[j] = 0; }
    if (j < 128 * 128) {
        int k = j >> 7, n = j & 127;
        g_wt[0 * 16384 + n * 128 + k] = __float2half(W0[j]);
        g_wt[1 * 16384 + n * 128 + k] = __float2half(W1[j]);
        g_wt[2 * 16384 + n * 128 + k] = __float2half(W2[j]);
        g_wt[3 * 16384 + n * 128 + k] = __float2half(W3[j]);
    }
}

__global__ void k_deg(const int* __restrict__ ei, const float* __restrict__ ew) {
    int i = blockIdx.x * blockDim.x + threadIdx.x;
    if (i >= NE) return;
    int d = ei[NE + i];
    if ((unsigned)d >= NN) return;
    atomicAdd(&g_deg[d], ew[i]);
    atomicAdd(&g_cnt[d], 1);
}

__global__ void k_bsum() {
    __shared__ int sh[SCAN_B];
    int i = blockIdx.x * SCAN_B + threadIdx.x;
    if (i < NN) {
        float dv = rsqrtf(g_deg[i]);
        g_deg[i] = dv;
        g_self[i] = 2.0f * dv * dv;
    }
    sh[threadIdx.x] = (i < NN) ? g_cnt[i] : 0;
    __syncthreads();
    for (int off = SCAN_B / 2; off > 0; off >>= 1) {
        if (threadIdx.x < off) sh[threadIdx.x] += sh[threadIdx.x + off];
        __syncthreads();
    }
    if (threadIdx.x == 0) g_bsum[blockIdx.x] = sh[0];
}

// row pointers: each block re-scans the 196 block sums (phase A), then scans
// its own 256 counts (phase B). Also emits graph bounds. k_bscan eliminated.
__global__ void k_ptr(const int* __restrict__ batch) {
    __shared__ int wsum[8];
    __shared__ int sboff;
    const int t = threadIdx.x;

    // phase A: inclusive scan of g_bsum over 256 lanes (>=NBLK)
    {
        int bv = (t < NBLK) ? g_bsum[t] : 0;
        int x = bv;
#pragma unroll
        for (int o = 1; o < 32; o <<= 1) {
            int y = __shfl_up_sync(0xffffffffu, x, o);
            if ((t & 31) >= o) x += y;
        }
        if ((t & 31) == 31) wsum[t >> 5] = x;
        __syncthreads();
        if (t < 8) {
            int y = wsum[t];
#pragma unroll
            for (int o = 1; o < 8; o <<= 1) {
                int z = __shfl_up_sync(0xffu, y, o);
                if (t >= o) y += z;
            }
            wsum[t] = y;
        }
        __syncthreads();
        int base = (t >= 32) ? wsum[(t >> 5) - 1] : 0;
        int inc = base + x;
        if (t == blockIdx.x) sboff = inc - bv;            // exclusive prefix
        if (blockIdx.x == 0 && t == NBLK - 1) g_ptr[NN] = inc;
        __syncthreads();
    }

    // phase B: per-block scan of counts
    int i = blockIdx.x * SCAN_B + t;
    int v = (i < NN) ? g_cnt[i] : 0;
    int x = v;
#pragma unroll
    for (int o = 1; o < 32; o <<= 1) {
        int y = __shfl_up_sync(0xffffffffu, x, o);
        if ((t & 31) >= o) x += y;
    }
    if ((t & 31) == 31) wsum[t >> 5] = x;
    __syncthreads();
    if (t < 8) {
        int y = wsum[t];
#pragma unroll
        for (int o = 1; o < 8; o <<= 1) {
            int z = __shfl_up_sync(0xffu, y, o);
            if (t >= o) y += z;
        }
        wsum[t] = y;
    }
    __syncthreads();
    int base = (t >= 32) ? wsum[(t >> 5) - 1] : 0;
    if (i < NN) {
        int p = sboff + base + x - v;
        g_ptr[i] = p;
        g_cur[i] = p;
        int g = batch[i];
        if ((unsigned)g < NG) {
            if (i == 0 || batch[i - 1] != g) g_gs[g] = i;
            if (i == NN - 1 || batch[i + 1] != g) g_ge[g] = i + 1;
        }
    }
}

__global__ void k_scatter(const int* __restrict__ ei, const float* __restrict__ ew) {
    int i = blockIdx.x * blockDim.x + threadIdx.x;
    if (i >= NE) return;
    int s = ei[i];
    int d = ei[NE + i];
    if ((unsigned)s >= NN || (unsigned)d >= NN) return;
    int pos = atomicAdd(&g_cur[d], 1);
    if ((unsigned)pos >= NE) return;
    g_srcA[pos] = s;
    g_normA[pos] = g_deg[s] * ew[i] * g_deg[d];
}

// ---------------- FP16 HMMA GEMM, 4m x 2n warp grid, ldmatrix ---------------
#define SK 136
#define GEMM_SMEM (2 * 128 * SK * (int)sizeof(__half))

__device__ __forceinline__ void mma_f16(float* c, unsigned a0, unsigned a1,
                                        unsigned a2, unsigned a3,
                                        unsigned b0, unsigned b1) {
    asm volatile(
        "mma.sync.aligned.m16n8k16.row.col.f32.f16.f16.f32 "
        "{%0,%1,%2,%3}, {%4,%5,%6,%7}, {%8,%9}, {%0,%1,%2,%3};"
        : "+f"(c[0]), "+f"(c[1]), "+f"(c[2]), "+f"(c[3])
        : "r"(a0), "r"(a1), "r"(a2), "r"(a3), "r"(b0), "r"(b1));
}

__device__ __forceinline__ void ldsm_x4(unsigned* r, unsigned addr) {
    asm volatile(
        "ldmatrix.sync.aligned.m8n8.x4.shared.b16 {%0,%1,%2,%3}, [%4];"
        : "=r"(r[0]), "=r"(r[1]), "=r"(r[2]), "=r"(r[3]) : "r"(addr));
}

__global__ __launch_bounds__(256) void k_gemm(const __half* __restrict__ A,
                                              const __half* __restrict__ Wt,
                                              __half* __restrict__ O, int nrows) {
    extern __shared__ __half smh[];
    __half* Wn = smh;            // [n][SK]
    __half* As = smh + 128 * SK; // [r][SK]
    const int tid = threadIdx.x;
    const int row0 = blockIdx.x * 128;

#pragma unroll
    for (int i = 0; i < 8; i++) {
        int u = tid + i * 256;
        int n = u >> 4, kq = u & 15;
        *(uint4*)(Wn + n * SK + kq * 8) = *(const uint4*)(Wt + n * 128 + kq * 8);
    }
#pragma unroll
    for (int i = 0; i < 8; i++) {
        int u = tid + i * 256;
        int r = u >> 4, kq = u & 15;
        int gr = row0 + r;
        uint4 v = (gr < nrows) ? *(const uint4*)(A + (size_t)gr * HD + kq * 8)
                               : make_uint4(0u, 0u, 0u, 0u);
        *(uint4*)(As + r * SK + kq * 8) = v;
    }
    __syncthreads();

    const int wid = tid >> 5, lane = tid & 31;
    const int mi = wid & 3;         // 4 M-tiles of 32 rows
    const int ni = wid >> 2;        // 2 N-halves of 64 cols
    const int warpRow = mi * 32;
    const int colBase = ni * 64;
    const int r = lane >> 2;
    const int q = lane & 3;

    unsigned aBase0 = (unsigned)__cvta_generic_to_shared(
        As + (warpRow + (lane & 15)) * SK + ((lane & 16) ? 8 : 0));
    unsigned aBase1 = aBase0 + 16 * SK * 2;   // rows +16
    unsigned bBase = (unsigned)__cvta_generic_to_shared(
        Wn + (colBase + (lane & 7)) * SK + ((lane >> 3) << 3));

    float acc[2][8][4];
#pragma unroll
    for (int rt = 0; rt < 2; rt++)
#pragma unroll
        for (int nt = 0; nt < 8; nt++) {
            acc[rt][nt][0] = 0.f; acc[rt][nt][1] = 0.f;
            acc[rt][nt][2] = 0.f; acc[rt][nt][3] = 0.f;
        }

#pragma unroll
    for (int k0 = 0; k0 < 128; k0 += 32) {
        unsigned a[2][8];
        ldsm_x4(a[0], aBase0 + k0 * 2);
        ldsm_x4(a[0] + 4, aBase0 + (k0 + 16) * 2);
        ldsm_x4(a[1], aBase1 + k0 * 2);
        ldsm_x4(a[1] + 4, aBase1 + (k0 + 16) * 2);
#pragma unroll
        for (int nt = 0; nt < 8; nt++) {
            unsigned b[4];
            ldsm_x4(b, bBase + (nt * 8 * SK + k0) * 2);
#pragma unroll
            for (int rt = 0; rt < 2; rt++) {
                mma_f16(acc[rt][nt], a[rt][0], a[rt][1], a[rt][2], a[rt][3], b[0], b[1]);
                mma_f16(acc[rt][nt], a[rt][4], a[rt][5], a[rt][6], a[rt][7], b[2], b[3]);
            }
        }
    }

#pragma unroll
    for (int rt = 0; rt < 2; rt++) {
        int orowA = row0 + warpRow + rt * 16 + r;
        int orowB = orowA + 8;
#pragma unroll
        for (int nt = 0; nt < 8; nt++) {
            int n = colBase + nt * 8 + q * 2;
            if (orowA < nrows)
                *(__half2*)(O + (size_t)orowA * HD + n) =
                    __floats2half2_rn(acc[rt][nt][0], acc[rt][nt][1]);
            if (orowB < nrows)
                *(__half2*)(O + (size_t)orowB * HD + n) =
                    __floats2half2_rn(acc[rt][nt][2], acc[rt][nt][3]);
        }
    }
}

// ---------------- aggregation: one warp per destination, 64-thr blocks ------
__global__ __launch_bounds__(64) void k_aggr(const __half* __restrict__ T,
                                             const float* __restrict__ bias,
                                             __half* __restrict__ Hout) {
    int gw = (blockIdx.x * blockDim.x + threadIdx.x) >> 5;
    if (gw >= NN) return;
    const int lane = threadIdx.x & 31;
    const int c = lane << 2;

    float sn = g_self[gw];
    uint2 tr = *(const uint2*)(T + (size_t)gw * HD + c);
    float2 ta = __half22float2(*(__half2*)&tr.x);
    float2 tb = __half22float2(*(__half2*)&tr.y);
    float4 acc = make_float4(ta.x * sn, ta.y * sn, tb.x * sn, tb.y * sn);

    int e = g_ptr[gw];
    const int e1 = g_ptr[gw + 1];
    for (; e + 3 < e1; e += 4) {
        int s0 = g_srcA[e], s1 = g_srcA[e + 1], s2 = g_srcA[e + 2], s3 = g_srcA[e + 3];
        float w0 = g_normA[e], w1 = g_normA[e + 1], w2 = g_normA[e + 2], w3 = g_normA[e + 3];
        uint2 r0 = *(const uint2*)(T + (size_t)s0 * HD + c);
        uint2 r1 = *(const uint2*)(T + (size_t)s1 * HD + c);
        uint2 r2 = *(const uint2*)(T + (size_t)s2 * HD + c);
        uint2 r3 = *(const uint2*)(T + (size_t)s3 * HD + c);
        float2 a0 = __half22float2(*(__half2*)&r0.x), b0 = __half22float2(*(__half2*)&r0.y);
        float2 a1 = __half22float2(*(__half2*)&r1.x), b1 = __half22float2(*(__half2*)&r1.y);
        float2 a2 = __half22float2(*(__half2*)&r2.x), b2 = __half22float2(*(__half2*)&r2.y);
        float2 a3 = __half22float2(*(__half2*)&r3.x), b3 = __half22float2(*(__half2*)&r3.y);
        acc.x += w0 * a0.x + w1 * a1.x + w2 * a2.x + w3 * a3.x;
        acc.y += w0 * a0.y + w1 * a1.y + w2 * a2.y + w3 * a3.y;
        acc.z += w0 * b0.x + w1 * b1.x + w2 * b2.x + w3 * b3.x;
        acc.w += w0 * b0.y + w1 * b1.y + w2 * b2.y + w3 * b3.y;
    }
    for (; e < e1; e++) {
        int s = g_srcA[e];
        float w = g_normA[e];
        uint2 rr = *(const uint2*)(T + (size_t)s * HD + c);
        float2 aa = __half22float2(*(__half2*)&rr.x);
        float2 bb2 = __half22float2(*(__half2*)&rr.y);
        acc.x += w * aa.x; acc.y += w * aa.y; acc.z += w * bb2.x; acc.w += w * bb2.y;
    }
    float4 bb = *(const float4*)(bias + c);
    __half2 o[2];
    o[0] = __floats2half2_rn(tanhf(acc.x + bb.x), tanhf(acc.y + bb.y));
    o[1] = __floats2half2_rn(tanhf(acc.z + bb.z), tanhf(acc.w + bb.w));
    *(uint2*)(Hout + (size_t)gw * HD + c) = *(uint2*)o;
}

// ---------------- readout + final dot + direct emit --------------------------
__global__ void k_readout(const __half* __restrict__ Hl, const float* __restrict__ Wout,
                          const float* __restrict__ bout, float* __restrict__ out,
                          int out_size) {
    __shared__ float red[128];
    int g = blockIdx.x;
    int c = threadIdx.x;    // 128
    int s = g_gs[g], e = g_ge[g];
    float vmax = -INFINITY, vsum = 0.0f;
    for (int i = s; i < e; i++) {
        float v = __half2float(Hl[(size_t)i * HD + c]);
        vmax = fmaxf(vmax, v);
        vsum += v;
    }
    int cnt = e - s;
    float hmax = (cnt > 0) ? vmax : 0.0f;
    float hmean = vsum / fmaxf((float)cnt, 1.0f);

    g_hidden[(size_t)g * 256 + c] = hmax;
    g_hidden[(size_t)g * 256 + 128 + c] = hmean;
    if (out_size >= NG + HID) {
        out[NG + (size_t)g * 256 + c] = hmax;
        out[NG + (size_t)g * 256 + 128 + c] = hmean;
    }

    red[c] = hmax * Wout[c] + hmean * Wout[128 + c];
    __syncthreads();
    for (int off = 64; off > 0; off >>= 1) {
        if (c < off) red[c] += red[c + off];
        __syncthreads();
    }
    if (c == 0) {
        float r = red[0] + bout[0];
        g_out[g] = r;
        if (out_size >= NG + HID) out[g] = r;
    }
}

// fallback for unexpected output layouts
__global__ void k_emit(float* __restrict__ out, int out_size) {
    int i = blockIdx.x * blockDim.x + threadIdx.x;
    if (i >= out_size) return;
    float v;
    if (out_size == HID) v = g_hidden[i];
    else v = (i < NG) ? g_out[i] : 0.0f;
    out[i] = v;
}

// ---------------- launch -----------------------------------------------------
extern "C" void kernel_launch(void* const* d_in, const int* in_sizes, int n_in,
                              void* d_out, int out_size) {
    const float* x     = (const float*)d_in[0];
    const int*   ei    = (const int*)d_in[1];
    const int*   batch = (const int*)d_in[2];
    const float* ew    = (const float*)d_in[3];
    const float* W[4] = { (const float*)d_in[4], (const float*)d_in[6],
                          (const float*)d_in[8], (const float*)d_in[10] };
    const float* B[4] = { (const float*)d_in[5], (const float*)d_in[7],
                          (const float*)d_in[9], (const float*)d_in[11] };
    const float* Wout = (const float*)d_in[12];
    const float* bout = (const float*)d_in[13];

    cudaFuncSetAttribute(k_gemm, cudaFuncAttributeMaxDynamicSharedMemorySize, GEMM_SMEM);

    __half *tbuf, *wt, *hA, *hB;
    cudaGetSymbolAddress((void**)&tbuf, g_t);
    cudaGetSymbolAddress((void**)&wt, g_wt);
    cudaGetSymbolAddress((void**)&hA, g_hA);
    cudaGetSymbolAddress((void**)&hB, g_hB);

    const int gemm_grid = (NN + 127) / 128;
    const int aggr_grid = (NN * 32 + 63) / 64;

    k_setup<<<(NN * HD / 8 + 255) / 256, 256>>>(x, hB, W[0], W[1], W[2], W[3]); // 0
    k_deg<<<(NE + 255) / 256, 256>>>(ei, ew);                                   // 1
    k_bsum<<<NBLK, SCAN_B>>>();                                                 // 2
    k_gemm<<<gemm_grid, 256, GEMM_SMEM>>>(hB, wt, tbuf, NN);                    // 3 <- profiled
    k_ptr<<<NBLK, SCAN_B>>>(batch);                                             // 4
    k_scatter<<<(NE + 255) / 256, 256>>>(ei, ew);                               // 5

    __half* ping[4] = { hA, hB, hA, hB };
    k_aggr<<<aggr_grid, 64>>>(tbuf, B[0], ping[0]);
    const __half* cur = ping[0];
    for (int l = 1; l < 4; l++) {
        k_gemm<<<gemm_grid, 256, GEMM_SMEM>>>(cur, wt + l * 16384, tbuf, NN);
        k_aggr<<<aggr_grid, 64>>>(tbuf, B[l], ping[l]);
        cur = ping[l];
    }

    k_readout<<<NG, 128>>>(cur, Wout, bout, (float*)d_out, out_size);
    if (out_size < NG + HID)
        k_emit<<<(out_size + 255) / 256, 256>>>((float*)d_out, out_size);
}